// round 2
// baseline (speedup 1.0000x reference)
#include <cuda_runtime.h>

#define N_TOK   32768
#define NBATCH  64
#define NPER    512
#define DQK     128
#define MF      256
#define DV      256

#define INV_D4      0.29730177875068026f  /* 128^-0.25 */
#define INV_SQRT_M  0.0625f               /* 1/sqrt(256) */
#define EPS_PHI     1e-4f
#define EPS_NORM    1e-8f

// ---------------- scratch (static device memory; no allocations) ----------------
__device__ float    g_Qp[N_TOK * MF];          // 33.6 MB
__device__ float    g_Kp[N_TOK * MF];          // 33.6 MB (Kp0 then scaled in-place)
__device__ float    g_rowmax[N_TOK];
__device__ unsigned g_segmax[NBATCH];          // order-encoded float max
__device__ float    g_KsumP[NBATCH * 4 * MF];  // 4 deterministic partials per batch
__device__ float    g_KV[NBATCH * MF * DV];    // 16.8 MB
__device__ float    g_norm[N_TOK];

// ---------------- helpers ----------------
__device__ __forceinline__ unsigned f2o(float f) {
    unsigned u = __float_as_uint(f);
    return (u & 0x80000000u) ? ~u : (u | 0x80000000u);
}
__device__ __forceinline__ float o2f(unsigned u) {
    return (u & 0x80000000u) ? __uint_as_float(u & 0x7fffffffu)
                             : __uint_as_float(~u);
}

// Packed dual-FMA (Blackwell f32x2) — 2 fp32 FMAs per instruction slot.
__device__ __forceinline__ void ffma2(float2& d, const float2 a, const float2 b) {
    asm("{\n\t"
        ".reg .b64 ra, rb, rd;\n\t"
        "mov.b64 ra, {%2, %3};\n\t"
        "mov.b64 rb, {%4, %5};\n\t"
        "mov.b64 rd, {%0, %1};\n\t"
        "fma.rn.f32x2 rd, ra, rb, rd;\n\t"
        "mov.b64 {%0, %1}, rd;\n\t"
        "}"
        : "+f"(d.x), "+f"(d.y)
        : "f"(a.x), "f"(a.y), "f"(b.x), "f"(b.y));
}

__device__ __forceinline__ float warpMax(float v) {
#pragma unroll
    for (int o = 16; o > 0; o >>= 1) v = fmaxf(v, __shfl_xor_sync(0xffffffffu, v, o));
    return v;
}
__device__ __forceinline__ float warpSum(float v) {
#pragma unroll
    for (int o = 16; o > 0; o >>= 1) v += __shfl_xor_sync(0xffffffffu, v, o);
    return v;
}

// ---------------- init ----------------
__global__ void init_kernel() {
    if (threadIdx.x < NBATCH) g_segmax[threadIdx.x] = 0u;  // 0 == "-inf" in f2o order
}

// ---------------- phi: U = (X*INV_D4)@omega, h, rowmax, exp ----------------
// Block: 256 thr, tile 64 rows x 256 cols (full feature width), K-chunks of 32.
// Thread (ty,tx): rows ty*8..+7, cols {tx*4..+3, 128+tx*4..+3}.
template <int ISQ>
__global__ __launch_bounds__(256)
void phi_kernel(const float* __restrict__ X, const float* __restrict__ omega)
{
    __shared__ float As[64 * 32];    // [row][k]
    __shared__ float Bs[32 * 256];   // [k][col]
    __shared__ float s_wmax[8];

    const int tid = threadIdx.x;
    const int ty  = tid >> 5;
    const int tx  = tid & 31;
    const int row0 = blockIdx.x * 64;

    float2 acc[8][4];
#pragma unroll
    for (int i = 0; i < 8; i++)
#pragma unroll
        for (int g = 0; g < 4; g++) acc[i][g] = make_float2(0.f, 0.f);
    float2 hacc[4];
#pragma unroll
    for (int j = 0; j < 4; j++) hacc[j] = make_float2(0.f, 0.f);

    for (int k0 = 0; k0 < DQK; k0 += 32) {
#pragma unroll
        for (int s = 0; s < 2; s++) {
            int idx = tid + s * 256;
            int r = idx >> 3, c4 = idx & 7;
            float4 v = *(const float4*)(X + (size_t)(row0 + r) * DQK + k0 + c4 * 4);
            v.x *= INV_D4; v.y *= INV_D4; v.z *= INV_D4; v.w *= INV_D4;
            *(float4*)(As + r * 32 + c4 * 4) = v;
        }
#pragma unroll
        for (int s = 0; s < 8; s++) {
            int idx = tid + s * 256;
            int r = idx >> 6, c4 = idx & 63;
            *(float4*)(Bs + r * 256 + c4 * 4) =
                *(const float4*)(omega + (size_t)(k0 + r) * 256 + c4 * 4);
        }
        __syncthreads();
#pragma unroll 4
        for (int kk = 0; kk < 32; kk++) {
            float a[8];
#pragma unroll
            for (int i = 0; i < 8; i++) a[i] = As[(ty * 8 + i) * 32 + kk];
#pragma unroll
            for (int j = 0; j < 4; j++) {
                float2 p = make_float2(a[2 * j], a[2 * j + 1]);
                ffma2(hacc[j], p, p);           // h accumulation (scaled-X sumsq)
            }
            float4 b0 = *(const float4*)(Bs + kk * 256 + tx * 4);
            float4 b1 = *(const float4*)(Bs + kk * 256 + 128 + tx * 4);
#pragma unroll
            for (int i = 0; i < 8; i++) {
                float2 aa = make_float2(a[i], a[i]);
                ffma2(acc[i][0], aa, make_float2(b0.x, b0.y));
                ffma2(acc[i][1], aa, make_float2(b0.z, b0.w));
                ffma2(acc[i][2], aa, make_float2(b1.x, b1.y));
                ffma2(acc[i][3], aa, make_float2(b1.z, b1.w));
            }
        }
        __syncthreads();
    }

    float* Out = ISQ ? g_Qp : g_Kp;
    float blockmax = -3.0e38f;
#pragma unroll
    for (int i = 0; i < 8; i++) {
        int row = row0 + ty * 8 + i;
        float mx = fmaxf(fmaxf(fmaxf(acc[i][0].x, acc[i][0].y), fmaxf(acc[i][1].x, acc[i][1].y)),
                         fmaxf(fmaxf(acc[i][2].x, acc[i][2].y), fmaxf(acc[i][3].x, acc[i][3].y)));
        mx = warpMax(mx);   // warp == full 256-col row
        float h  = 0.5f * ((i & 1) ? hacc[i >> 1].y : hacc[i >> 1].x);
        float hm = h + mx;
        float4 o0, o1;
        if (ISQ) {
            o0.x = (__expf(acc[i][0].x - hm) + EPS_PHI) * INV_SQRT_M;
            o0.y = (__expf(acc[i][0].y - hm) + EPS_PHI) * INV_SQRT_M;
            o0.z = (__expf(acc[i][1].x - hm) + EPS_PHI) * INV_SQRT_M;
            o0.w = (__expf(acc[i][1].y - hm) + EPS_PHI) * INV_SQRT_M;
            o1.x = (__expf(acc[i][2].x - hm) + EPS_PHI) * INV_SQRT_M;
            o1.y = (__expf(acc[i][2].y - hm) + EPS_PHI) * INV_SQRT_M;
            o1.z = (__expf(acc[i][3].x - hm) + EPS_PHI) * INV_SQRT_M;
            o1.w = (__expf(acc[i][3].y - hm) + EPS_PHI) * INV_SQRT_M;
        } else {
            // Kp0 = exp(U - h - rowmax); eps/scale applied after segmax is known
            o0.x = __expf(acc[i][0].x - hm);
            o0.y = __expf(acc[i][0].y - hm);
            o0.z = __expf(acc[i][1].x - hm);
            o0.w = __expf(acc[i][1].y - hm);
            o1.x = __expf(acc[i][2].x - hm);
            o1.y = __expf(acc[i][2].y - hm);
            o1.z = __expf(acc[i][3].x - hm);
            o1.w = __expf(acc[i][3].y - hm);
            if (tx == 0) g_rowmax[row] = mx;
            blockmax = fmaxf(blockmax, mx);
        }
        *(float4*)(Out + (size_t)row * MF + tx * 4)       = o0;
        *(float4*)(Out + (size_t)row * MF + 128 + tx * 4) = o1;
    }
    if (!ISQ) {
        if (tx == 0) s_wmax[ty] = blockmax;
        __syncthreads();
        if (tid == 0) {
            float bm = s_wmax[0];
#pragma unroll
            for (int w = 1; w < 8; w++) bm = fmaxf(bm, s_wmax[w]);
            atomicMax(&g_segmax[row0 >> 9], f2o(bm));  // 64 rows per block share a segment
        }
    }
}

// ---------------- rescale K: Kp = (Kp0 * exp(rowmax - segmax) + eps)/sqrt(m) ----------------
__global__ __launch_bounds__(512)
void scalek_kernel()
{
    int idx = blockIdx.x * 512 + threadIdx.x;   // float4 index, 2,097,152 total
    int row = idx >> 6;
    float s = __expf(g_rowmax[row] - o2f(g_segmax[row >> 9]));
    float4 v = *(float4*)(g_Kp + (size_t)idx * 4);
    v.x = (v.x * s + EPS_PHI) * INV_SQRT_M;
    v.y = (v.y * s + EPS_PHI) * INV_SQRT_M;
    v.z = (v.z * s + EPS_PHI) * INV_SQRT_M;
    v.w = (v.w * s + EPS_PHI) * INV_SQRT_M;
    *(float4*)(g_Kp + (size_t)idx * 4) = v;
}

// ---------------- Ksum partials (deterministic, 4 per batch) ----------------
__global__ __launch_bounds__(256)
void ksum_kernel()
{
    int b = blockIdx.x, p = blockIdx.y, j = threadIdx.x;
    const float* Kp = g_Kp + ((size_t)b * NPER + p * 128) * MF + j;
    float s0 = 0.f, s1 = 0.f, s2 = 0.f, s3 = 0.f;
#pragma unroll 4
    for (int n = 0; n < 128; n += 4) {
        s0 += Kp[(n + 0) * MF];
        s1 += Kp[(n + 1) * MF];
        s2 += Kp[(n + 2) * MF];
        s3 += Kp[(n + 3) * MF];
    }
    g_KsumP[(b * 4 + p) * MF + j] = (s0 + s1) + (s2 + s3);
}

// ---------------- KV = Kp_b^T @ V_b : per block 64(m) x 256(v), K over n=512 ----------------
__global__ __launch_bounds__(256)
void kv_kernel(const float* __restrict__ V)
{
    __shared__ float As[32 * 64];    // [n][mm]
    __shared__ float Bs[32 * 256];   // [n][vv]
    const int tid = threadIdx.x;
    const int ty  = tid >> 5;
    const int tx  = tid & 31;
    const int b   = blockIdx.x >> 2;
    const int mm0 = (blockIdx.x & 3) * 64;
    const float* Kp = g_Kp + (size_t)b * NPER * MF;
    const float* Vb = V + (size_t)b * NPER * DV;

    float2 acc[8][4];
#pragma unroll
    for (int i = 0; i < 8; i++)
#pragma unroll
        for (int g = 0; g < 4; g++) acc[i][g] = make_float2(0.f, 0.f);

    for (int n0 = 0; n0 < NPER; n0 += 32) {
#pragma unroll
        for (int s = 0; s < 2; s++) {
            int idx = tid + s * 256;
            int r = idx >> 4, c4 = idx & 15;
            *(float4*)(As + r * 64 + c4 * 4) =
                *(const float4*)(Kp + (size_t)(n0 + r) * MF + mm0 + c4 * 4);
        }
#pragma unroll
        for (int s = 0; s < 8; s++) {
            int idx = tid + s * 256;
            int r = idx >> 6, c4 = idx & 63;
            *(float4*)(Bs + r * 256 + c4 * 4) =
                *(const float4*)(Vb + (size_t)(n0 + r) * DV + c4 * 4);
        }
        __syncthreads();
#pragma unroll 4
        for (int kk = 0; kk < 32; kk++) {
            float a[8];
#pragma unroll
            for (int i = 0; i < 8; i++) a[i] = As[kk * 64 + ty * 8 + i];
            float4 b0 = *(const float4*)(Bs + kk * 256 + tx * 4);
            float4 b1 = *(const float4*)(Bs + kk * 256 + 128 + tx * 4);
#pragma unroll
            for (int i = 0; i < 8; i++) {
                float2 aa = make_float2(a[i], a[i]);
                ffma2(acc[i][0], aa, make_float2(b0.x, b0.y));
                ffma2(acc[i][1], aa, make_float2(b0.z, b0.w));
                ffma2(acc[i][2], aa, make_float2(b1.x, b1.y));
                ffma2(acc[i][3], aa, make_float2(b1.z, b1.w));
            }
        }
        __syncthreads();
    }

    float* C = g_KV + (size_t)b * MF * DV;
#pragma unroll
    for (int i = 0; i < 8; i++) {
        int mm = mm0 + ty * 8 + i;
        float4 o0 = make_float4(acc[i][0].x, acc[i][0].y, acc[i][1].x, acc[i][1].y);
        float4 o1 = make_float4(acc[i][2].x, acc[i][2].y, acc[i][3].x, acc[i][3].y);
        *(float4*)(C + (size_t)mm * DV + tx * 4)       = o0;
        *(float4*)(C + (size_t)mm * DV + 128 + tx * 4) = o1;
    }
}

// ---------------- norm[i] = Qp[i] . Ksum[seg(i)] + eps (warp per row) ----------------
__global__ __launch_bounds__(256)
void norm_kernel()
{
    const int tid = threadIdx.x;
    const int ty  = tid >> 5;
    const int tx  = tid & 31;
    const int row = blockIdx.x * 8 + ty;
    const int b   = row >> 9;
    const float* P = g_KsumP + (size_t)b * 4 * MF;

    float4 q0 = *(const float4*)(g_Qp + (size_t)row * MF + tx * 4);
    float4 q1 = *(const float4*)(g_Qp + (size_t)row * MF + 128 + tx * 4);
    float4 k0 = make_float4(0.f, 0.f, 0.f, 0.f), k1 = k0;
#pragma unroll
    for (int p = 0; p < 4; p++) {
        float4 a = *(const float4*)(P + p * MF + tx * 4);
        float4 c = *(const float4*)(P + p * MF + 128 + tx * 4);
        k0.x += a.x; k0.y += a.y; k0.z += a.z; k0.w += a.w;
        k1.x += c.x; k1.y += c.y; k1.z += c.z; k1.w += c.w;
    }
    float dot = q0.x * k0.x + q0.y * k0.y + q0.z * k0.z + q0.w * k0.w
              + q1.x * k1.x + q1.y * k1.y + q1.z * k1.z + q1.w * k1.w;
    dot = warpSum(dot);
    if (tx == 0) g_norm[row] = dot + EPS_NORM;
}

// ---------------- out = (Qp_b @ KV_b) / norm : per block 64 rows x 256 cols ----------------
__global__ __launch_bounds__(256)
void out_kernel(float* __restrict__ Out)
{
    __shared__ float As[64 * 32];    // [r][k]
    __shared__ float Bs[32 * 256];   // [k][vv]
    const int tid = threadIdx.x;
    const int ty  = tid >> 5;
    const int tx  = tid & 31;
    const int b   = blockIdx.x >> 3;
    const int row0 = b * NPER + (blockIdx.x & 7) * 64;
    const float* KV = g_KV + (size_t)b * MF * DV;

    float2 acc[8][4];
#pragma unroll
    for (int i = 0; i < 8; i++)
#pragma unroll
        for (int g = 0; g < 4; g++) acc[i][g] = make_float2(0.f, 0.f);

    for (int k0 = 0; k0 < MF; k0 += 32) {
#pragma unroll
        for (int s = 0; s < 2; s++) {
            int idx = tid + s * 256;
            int r = idx >> 3, c4 = idx & 7;
            *(float4*)(As + r * 32 + c4 * 4) =
                *(const float4*)(g_Qp + (size_t)(row0 + r) * MF + k0 + c4 * 4);
        }
#pragma unroll
        for (int s = 0; s < 8; s++) {
            int idx = tid + s * 256;
            int r = idx >> 6, c4 = idx & 63;
            *(float4*)(Bs + r * 256 + c4 * 4) =
                *(const float4*)(KV + (size_t)(k0 + r) * DV + c4 * 4);
        }
        __syncthreads();
#pragma unroll 4
        for (int kk = 0; kk < 32; kk++) {
            float a[8];
#pragma unroll
            for (int i = 0; i < 8; i++) a[i] = As[(ty * 8 + i) * 32 + kk];
            float4 b0 = *(const float4*)(Bs + kk * 256 + tx * 4);
            float4 b1 = *(const float4*)(Bs + kk * 256 + 128 + tx * 4);
#pragma unroll
            for (int i = 0; i < 8; i++) {
                float2 aa = make_float2(a[i], a[i]);
                ffma2(acc[i][0], aa, make_float2(b0.x, b0.y));
                ffma2(acc[i][1], aa, make_float2(b0.z, b0.w));
                ffma2(acc[i][2], aa, make_float2(b1.x, b1.y));
                ffma2(acc[i][3], aa, make_float2(b1.z, b1.w));
            }
        }
        __syncthreads();
    }

#pragma unroll
    for (int i = 0; i < 8; i++) {
        int row = row0 + ty * 8 + i;
        float inv = 1.0f / g_norm[row];
        float4 o0 = make_float4(acc[i][0].x * inv, acc[i][0].y * inv,
                                acc[i][1].x * inv, acc[i][1].y * inv);
        float4 o1 = make_float4(acc[i][2].x * inv, acc[i][2].y * inv,
                                acc[i][3].x * inv, acc[i][3].y * inv);
        *(float4*)(Out + (size_t)row * DV + tx * 4)       = o0;
        *(float4*)(Out + (size_t)row * DV + 128 + tx * 4) = o1;
    }
}

// ---------------- launch ----------------
extern "C" void kernel_launch(void* const* d_in, const int* in_sizes, int n_in,
                              void* d_out, int out_size)
{
    (void)in_sizes; (void)n_in; (void)out_size;
    const float* Q     = (const float*)d_in[0];
    const float* K     = (const float*)d_in[1];
    const float* V     = (const float*)d_in[2];
    const float* omega = (const float*)d_in[3];
    float* Out = (float*)d_out;

    init_kernel<<<1, 64>>>();
    phi_kernel<1><<<N_TOK / 64, 256>>>(Q, omega);
    phi_kernel<0><<<N_TOK / 64, 256>>>(K, omega);
    scalek_kernel<<<(N_TOK * MF / 4) / 512, 512>>>();
    ksum_kernel<<<dim3(NBATCH, 4), 256>>>();
    kv_kernel<<<NBATCH * 4, 256>>>(V);
    norm_kernel<<<N_TOK / 8, 256>>>();
    out_kernel<<<NBATCH * 8, 256>>>(Out);
}

// round 4
// speedup vs baseline: 1.1649x; 1.1649x over previous
#include <cuda_runtime.h>
#include <cuda_bf16.h>
#include <cstdint>

#define N_TOK   32768
#define NBATCH  64
#define NPER    512
#define DQK     128
#define MF      256
#define DV      256
#define PAD     136   /* bf16 row stride in smem (272B): conflict-free ldmatrix */

#define INV_D4      0.29730177875068026f
#define INV_SQRT_M  0.0625f
#define EPS_PHI     1e-4f
#define EPS_NORM    1e-8f

// ---------------- scratch ----------------
__device__ uint32_t g_Qp  [(size_t)N_TOK * MF];      // packed (hi | lo<<16), [token][feat]
__device__ uint32_t g_Kp0 [(size_t)N_TOK * MF];      // pre-rescale Kp0 packed, [token][feat]
__device__ uint32_t g_KpT [(size_t)MF * N_TOK];      // packed, [feat][token]
__device__ uint32_t g_VT  [(size_t)DV * N_TOK];      // packed, [v][token]
__device__ uint32_t g_omT [(size_t)MF * DQK];        // packed, [feat][k]
__device__ uint32_t g_KVT [(size_t)NBATCH * DV * MF];// packed, [b][v][m]
__device__ float    g_rowmax[N_TOK];
__device__ unsigned g_segmax[NBATCH];
__device__ float    g_KsumP[256 * MF];               // per 128-token tile, per feature
__device__ float    g_norm[N_TOK];

// ---------------- helpers ----------------
__device__ __forceinline__ uint32_t smem_u32(const void* p) {
    uint32_t a;
    asm("{ .reg .u64 t; cvta.to.shared.u64 t, %1; cvt.u32.u64 %0, t; }" : "=r"(a) : "l"(p));
    return a;
}
__device__ __forceinline__ void ldsm4(uint32_t* r, uint32_t a) {
    asm volatile("ldmatrix.sync.aligned.m8n8.x4.shared.b16 {%0,%1,%2,%3}, [%4];"
        : "=r"(r[0]), "=r"(r[1]), "=r"(r[2]), "=r"(r[3]) : "r"(a));
}
__device__ __forceinline__ void mma16816(float* c, const uint32_t* a, const uint32_t* b) {
    asm volatile("mma.sync.aligned.m16n8k16.row.col.f32.bf16.bf16.f32 "
        "{%0,%1,%2,%3}, {%4,%5,%6,%7}, {%8,%9}, {%0,%1,%2,%3};"
        : "+f"(c[0]), "+f"(c[1]), "+f"(c[2]), "+f"(c[3])
        : "r"(a[0]), "r"(a[1]), "r"(a[2]), "r"(a[3]), "r"(b[0]), "r"(b[1]));
}
__device__ __forceinline__ uint32_t pack_split(float v) {
    __nv_bfloat16 h = __float2bfloat16(v);
    __nv_bfloat16 l = __float2bfloat16(v - __bfloat162float(h));
    return (uint32_t)__bfloat16_as_ushort(h) | ((uint32_t)__bfloat16_as_ushort(l) << 16);
}
__device__ __forceinline__ float unpack_val(uint32_t p) {
    return __bfloat162float(__ushort_as_bfloat16((unsigned short)(p & 0xffffu)))
         + __bfloat162float(__ushort_as_bfloat16((unsigned short)(p >> 16)));
}
__device__ __forceinline__ void split2(uint2 p, uint32_t& hi2, uint32_t& lo2) {
    hi2 = (p.x & 0xffffu) | (p.y << 16);
    lo2 = (p.x >> 16) | (p.y & 0xffff0000u);
}
__device__ __forceinline__ unsigned f2o(float f) {
    unsigned u = __float_as_uint(f);
    return (u & 0x80000000u) ? ~u : (u | 0x80000000u);
}
__device__ __forceinline__ float o2f(unsigned u) {
    return (u & 0x80000000u) ? __uint_as_float(u & 0x7fffffffu) : __uint_as_float(~u);
}
__device__ __forceinline__ float warpSum(float v) {
#pragma unroll
    for (int o = 16; o > 0; o >>= 1) v += __shfl_xor_sync(0xffffffffu, v, o);
    return v;
}
__device__ __forceinline__ float warpMax(float v) {
#pragma unroll
    for (int o = 16; o > 0; o >>= 1) v = fmaxf(v, __shfl_xor_sync(0xffffffffu, v, o));
    return v;
}

// ---------------- warp-tiled bf16x3 GEMM core: one K=128 chunk ----------------
// Block tile 128x128, 8 warps (4 m x 2 n), warp tile 32x64.
// A,B smem: bf16 [128][PAD], K-contiguous. C = Ah*Bh + Ah*Bl + Al*Bh.
__device__ __forceinline__ void gemm128(float c[2][8][4],
    uint32_t Ahi, uint32_t Alo, uint32_t Bhi, uint32_t Blo,
    int lane, int m0, int n0)
{
    uint32_t ao[2], bo[4];
#pragma unroll
    for (int mt = 0; mt < 2; mt++)
        ao[mt] = (uint32_t)((m0 + mt * 16 + (lane & 15)) * PAD + (lane >> 4) * 8) * 2u;
#pragma unroll
    for (int n2 = 0; n2 < 4; n2++)
        bo[n2] = (uint32_t)((n0 + n2 * 16 + ((lane >> 4) << 3) + (lane & 7)) * PAD
                            + ((lane >> 3) & 1) * 8) * 2u;
#pragma unroll
    for (int ks = 0; ks < 8; ks++) {
        uint32_t ah[2][4], al[2][4], bh[4][4], bl[4][4];
#pragma unroll
        for (int mt = 0; mt < 2; mt++) {
            ldsm4(ah[mt], Ahi + ao[mt] + ks * 32);
            ldsm4(al[mt], Alo + ao[mt] + ks * 32);
        }
#pragma unroll
        for (int n2 = 0; n2 < 4; n2++) {
            ldsm4(bh[n2], Bhi + bo[n2] + ks * 32);
            ldsm4(bl[n2], Blo + bo[n2] + ks * 32);
        }
#pragma unroll
        for (int mt = 0; mt < 2; mt++)
#pragma unroll
            for (int nt = 0; nt < 8; nt++) {
                const uint32_t* bph = &bh[nt >> 1][(nt & 1) * 2];
                const uint32_t* bpl = &bl[nt >> 1][(nt & 1) * 2];
                mma16816(c[mt][nt], ah[mt], bph);
                mma16816(c[mt][nt], ah[mt], bpl);
                mma16816(c[mt][nt], al[mt], bph);
            }
    }
}

// stage a 128x128 tile from packed global (row stride gstride u32) into hi/lo smem
__device__ __forceinline__ void stage_packed(char* hi, char* lo,
    const uint32_t* __restrict__ gsrc, size_t gstride, int tid)
{
#pragma unroll 4
    for (int i = 0; i < 32; i++) {
        int f = i * 256 + tid, r = f >> 6, k2 = (f & 63) * 2;
        uint2 p = *(const uint2*)(gsrc + (size_t)r * gstride + k2);
        uint32_t h2, l2; split2(p, h2, l2);
        uint32_t off = (uint32_t)(r * PAD + k2) * 2u;
        *(uint32_t*)(hi + off) = h2;
        *(uint32_t*)(lo + off) = l2;
    }
}

// store C fragments to f32 smem buffer stride 129
__device__ __forceinline__ void frag_to_dbuf(float* dbuf, const float c[2][8][4],
                                             int lane, int m0, int n0)
{
    int g = lane >> 2, j = lane & 3;
#pragma unroll
    for (int mt = 0; mt < 2; mt++)
#pragma unroll
        for (int nt = 0; nt < 8; nt++) {
            int r0 = m0 + mt * 16 + g, cc = n0 + nt * 8 + j * 2;
            dbuf[r0 * 129 + cc]           = c[mt][nt][0];
            dbuf[r0 * 129 + cc + 1]       = c[mt][nt][1];
            dbuf[(r0 + 8) * 129 + cc]     = c[mt][nt][2];
            dbuf[(r0 + 8) * 129 + cc + 1] = c[mt][nt][3];
        }
}

// ---------------- init ----------------
__global__ void init_kernel() {
    if (threadIdx.x < NBATCH) g_segmax[threadIdx.x] = 0u;
}

// ---------------- omega^T: [128k][256m] f32 -> g_omT [m][k] packed ----------------
__global__ __launch_bounds__(256)
void omT_kernel(const float* __restrict__ omega) {
    extern __shared__ char smem[];
    float* tile = (float*)smem;                       // [128][257]
    const int tid = threadIdx.x;
    for (int i = 0; i < 128; i++) {
        int f = i * 256 + tid, k = f >> 8, n = f & 255;
        tile[k * 257 + n] = omega[k * MF + n];
    }
    __syncthreads();
    for (int i = 0; i < 128; i++) {
        int f = i * 256 + tid, n = f >> 7, k = f & 127;
        g_omT[n * DQK + k] = pack_split(tile[k * 257 + n]);
    }
}

// ---------------- V^T: tiles [128n][128v] -> g_VT [v][n] packed ----------------
__global__ __launch_bounds__(256)
void vT_kernel(const float* __restrict__ V) {
    extern __shared__ char smem[];
    float* tile = (float*)smem;                       // [128][129]
    const int tid = threadIdx.x;
    const int n0 = blockIdx.x * 128, v0 = blockIdx.y * 128;
    for (int i = 0; i < 64; i++) {
        int f = i * 256 + tid, n = f >> 7, v = f & 127;
        tile[n * 129 + v] = V[(size_t)(n0 + n) * DV + v0 + v];
    }
    __syncthreads();
    for (int i = 0; i < 64; i++) {
        int f = i * 256 + tid, v = f >> 7, n = f & 127;
        g_VT[(size_t)(v0 + v) * N_TOK + n0 + n] = pack_split(tile[n * 129 + v]);
    }
}

// ---------------- phi: U = (X/d^.25)@omega via HMMA bf16x3, + h, rowmax, exp ----------------
// CTA 256 thr: 128 tokens x 256 feats (two N=128 passes), K=128.
#define PHI_A_HI  2176
#define PHI_A_LO  (PHI_A_HI + 34816)
#define PHI_B_HI  (PHI_A_LO + 34816)
#define PHI_B_LO  (PHI_B_HI + 34816)
#define PHI_UBUF  (PHI_B_LO + 34816)
#define PHI_SMEM  (PHI_UBUF + 128 * 129 * 4)

template <int ISQ>
__global__ __launch_bounds__(256, 1)
void phi_kernel(const float* __restrict__ X)
{
    extern __shared__ char smem[];
    const uint32_t sb = smem_u32(smem);
    const int tid = threadIdx.x, wid = tid >> 5, lane = tid & 31;
    const int row0 = blockIdx.x * 128;
    const int m0 = (wid & 3) * 32, n0 = (wid >> 2) * 64, warpN = wid >> 2;

    float* h_sm    = (float*)smem;               // [128]
    float* rmax_sm = (float*)(smem + 512);       // [128]
    float* rmaxp   = (float*)(smem + 1024);      // [128][2]
    float* wm_sm   = (float*)(smem + 2048);      // [4]
    float* ubuf    = (float*)(smem + PHI_UBUF);  // [128][129]

    // stage A: load X, scale, h per row, split hi/lo
#pragma unroll 2
    for (int i = 0; i < 16; i++) {
        int row = i * 8 + wid;
        float4 v = ((const float4*)(X + (size_t)(row0 + row) * DQK))[lane];
        v.x *= INV_D4; v.y *= INV_D4; v.z *= INV_D4; v.w *= INV_D4;
        float hs = warpSum(v.x * v.x + v.y * v.y + v.z * v.z + v.w * v.w);
        if (lane == 0) h_sm[row] = 0.5f * hs;
        uint32_t p0 = pack_split(v.x), p1 = pack_split(v.y);
        uint32_t p2 = pack_split(v.z), p3 = pack_split(v.w);
        uint32_t h2a = (p0 & 0xffffu) | (p1 << 16), l2a = (p0 >> 16) | (p1 & 0xffff0000u);
        uint32_t h2b = (p2 & 0xffffu) | (p3 << 16), l2b = (p2 >> 16) | (p3 & 0xffff0000u);
        uint32_t off = (uint32_t)(row * PAD + lane * 4) * 2u;
        *(uint2*)(smem + PHI_A_HI + off) = make_uint2(h2a, h2b);
        *(uint2*)(smem + PHI_A_LO + off) = make_uint2(l2a, l2b);
    }

    float rmx[2][2] = {{-3.0e38f, -3.0e38f}, {-3.0e38f, -3.0e38f}};

    // ---- pass 0: feats 0..127 ----
    stage_packed(smem + PHI_B_HI, smem + PHI_B_LO, g_omT, DQK, tid);
    __syncthreads();
    {
        float c[2][8][4];
#pragma unroll
        for (int mt = 0; mt < 2; mt++)
#pragma unroll
            for (int nt = 0; nt < 8; nt++)
#pragma unroll
                for (int q = 0; q < 4; q++) c[mt][nt][q] = 0.f;
        gemm128(c, sb + PHI_A_HI, sb + PHI_A_LO, sb + PHI_B_HI, sb + PHI_B_LO, lane, m0, n0);
#pragma unroll
        for (int mt = 0; mt < 2; mt++)
#pragma unroll
            for (int nt = 0; nt < 8; nt++) {
                rmx[mt][0] = fmaxf(rmx[mt][0], fmaxf(c[mt][nt][0], c[mt][nt][1]));
                rmx[mt][1] = fmaxf(rmx[mt][1], fmaxf(c[mt][nt][2], c[mt][nt][3]));
            }
        frag_to_dbuf(ubuf, c, lane, m0, n0);
    }
    __syncthreads();

    // ---- pass 1: feats 128..255 ----
    stage_packed(smem + PHI_B_HI, smem + PHI_B_LO, g_omT + (size_t)128 * DQK, DQK, tid);
    __syncthreads();
    float c[2][8][4];
#pragma unroll
    for (int mt = 0; mt < 2; mt++)
#pragma unroll
        for (int nt = 0; nt < 8; nt++)
#pragma unroll
            for (int q = 0; q < 4; q++) c[mt][nt][q] = 0.f;
    gemm128(c, sb + PHI_A_HI, sb + PHI_A_LO, sb + PHI_B_HI, sb + PHI_B_LO, lane, m0, n0);
#pragma unroll
    for (int mt = 0; mt < 2; mt++)
#pragma unroll
        for (int nt = 0; nt < 8; nt++) {
            rmx[mt][0] = fmaxf(rmx[mt][0], fmaxf(c[mt][nt][0], c[mt][nt][1]));
            rmx[mt][1] = fmaxf(rmx[mt][1], fmaxf(c[mt][nt][2], c[mt][nt][3]));
        }

    // rowmax: reduce within quads (lanes sharing row group g)
#pragma unroll
    for (int mt = 0; mt < 2; mt++)
#pragma unroll
        for (int hh = 0; hh < 2; hh++) {
            float v = rmx[mt][hh];
            v = fmaxf(v, __shfl_xor_sync(0xffffffffu, v, 1));
            v = fmaxf(v, __shfl_xor_sync(0xffffffffu, v, 2));
            rmx[mt][hh] = v;
        }
    {
        int g = lane >> 2;
        if ((lane & 3) == 0) {
            rmaxp[(m0 + g) * 2 + warpN]      = rmx[0][0];
            rmaxp[(m0 + g + 8) * 2 + warpN]  = rmx[0][1];
            rmaxp[(m0 + 16 + g) * 2 + warpN] = rmx[1][0];
            rmaxp[(m0 + 24 + g) * 2 + warpN] = rmx[1][1];
        }
    }
    __syncthreads();
    if (tid < 128) {
        float rm = fmaxf(rmaxp[tid * 2], rmaxp[tid * 2 + 1]);
        rmax_sm[tid] = rm;
        if (!ISQ) {
            g_rowmax[row0 + tid] = rm;
            float bm = warpMax(rm);
            if (lane == 0) wm_sm[wid] = bm;
        }
    }
    __syncthreads();

    // epilogue pass-1 (regs): cols 128..255
    uint32_t* dst = ISQ ? g_Qp : g_Kp0;
    {
        int g = lane >> 2, j = lane & 3;
#pragma unroll
        for (int mt = 0; mt < 2; mt++) {
            int r0 = m0 + mt * 16 + g, r1 = r0 + 8;
            float hm0 = h_sm[r0] + rmax_sm[r0];
            float hm1 = h_sm[r1] + rmax_sm[r1];
#pragma unroll
            for (int nt = 0; nt < 8; nt++) {
                int col = 128 + n0 + nt * 8 + j * 2;
                float v0, v1, v2, v3;
                if (ISQ) {
                    v0 = (__expf(c[mt][nt][0] - hm0) + EPS_PHI) * INV_SQRT_M;
                    v1 = (__expf(c[mt][nt][1] - hm0) + EPS_PHI) * INV_SQRT_M;
                    v2 = (__expf(c[mt][nt][2] - hm1) + EPS_PHI) * INV_SQRT_M;
                    v3 = (__expf(c[mt][nt][3] - hm1) + EPS_PHI) * INV_SQRT_M;
                } else {
                    v0 = __expf(c[mt][nt][0] - hm0);
                    v1 = __expf(c[mt][nt][1] - hm0);
                    v2 = __expf(c[mt][nt][2] - hm1);
                    v3 = __expf(c[mt][nt][3] - hm1);
                }
                *(uint2*)&dst[(size_t)(row0 + r0) * MF + col] =
                    make_uint2(pack_split(v0), pack_split(v1));
                *(uint2*)&dst[(size_t)(row0 + r1) * MF + col] =
                    make_uint2(pack_split(v2), pack_split(v3));
            }
        }
    }
    // epilogue pass-0 (ubuf): cols 0..127
#pragma unroll 2
    for (int i = 0; i < 64; i++) {
        int f = i * 256 + tid, r = f >> 7, cc = f & 127;
        float hm = h_sm[r] + rmax_sm[r];
        float u = ubuf[r * 129 + cc];
        float val = ISQ ? (__expf(u - hm) + EPS_PHI) * INV_SQRT_M : __expf(u - hm);
        dst[(size_t)(row0 + r) * MF + cc] = pack_split(val);
    }
    if (!ISQ && tid == 0) {
        float bm = fmaxf(fmaxf(wm_sm[0], wm_sm[1]), fmaxf(wm_sm[2], wm_sm[3]));
        atomicMax(&g_segmax[row0 >> 9], f2o(bm));
    }
}

// ---------------- scalekT: Kp0 -> KpT (rescale + eps + transpose) + Ksum ----------------
__global__ __launch_bounds__(256)
void scalekT_kernel()
{
    extern __shared__ char smem[];
    float* sfac = (float*)smem;                        // [128]
    uint32_t* tile = (uint32_t*)(smem + 1024);         // [128][257]
    const int tid = threadIdx.x;
    const int nt = blockIdx.x, n0 = nt * 128;
    if (tid < 128) sfac[tid] = __expf(g_rowmax[n0 + tid] - o2f(g_segmax[n0 >> 9]));
#pragma unroll 4
    for (int i = 0; i < 128; i++) {
        int f = i * 256 + tid, n = f >> 8, m = f & 255;
        tile[n * 257 + m] = g_Kp0[(size_t)(n0 + n) * MF + m];
    }
    __syncthreads();
#pragma unroll 4
    for (int i = 0; i < 128; i++) {
        int f = i * 256 + tid, m = f >> 7, nn = f & 127;
        float v = (unpack_val(tile[nn * 257 + m]) * sfac[nn] + EPS_PHI) * INV_SQRT_M;
        g_KpT[(size_t)m * N_TOK + n0 + nn] = pack_split(v);
    }
    float s = 0.f;
#pragma unroll 4
    for (int nn = 0; nn < 128; nn++)
        s += (unpack_val(tile[nn * 257 + tid]) * sfac[nn] + EPS_PHI) * INV_SQRT_M;
    g_KsumP[nt * 256 + tid] = s;
}

// ---------------- KV: D[m=128][v=128] = sum_n KpT[m][n]*VT[v][n] ----------------
#define KV_A_HI  0
#define KV_A_LO  34816
#define KV_B_HI  69632
#define KV_B_LO  104448
#define KV_SMEM  139776

__global__ __launch_bounds__(256, 1)
void kv_kernel()
{
    extern __shared__ char smem[];
    const uint32_t sb = smem_u32(smem);
    const int tid = threadIdx.x, wid = tid >> 5, lane = tid & 31;
    const int b = blockIdx.x >> 2, mt_ = (blockIdx.x >> 1) & 1, vt = blockIdx.x & 1;
    const int m0g = mt_ * 128, v0 = vt * 128;
    const int m0 = (wid & 3) * 32, n0 = (wid >> 2) * 64;

    float c[2][8][4];
#pragma unroll
    for (int mt = 0; mt < 2; mt++)
#pragma unroll
        for (int nt = 0; nt < 8; nt++)
#pragma unroll
            for (int q = 0; q < 4; q++) c[mt][nt][q] = 0.f;

    for (int ch = 0; ch < 4; ch++) {
        __syncthreads();
        stage_packed(smem + KV_A_HI, smem + KV_A_LO,
                     g_KpT + (size_t)m0g * N_TOK + (size_t)b * NPER + ch * 128, N_TOK, tid);
        stage_packed(smem + KV_B_HI, smem + KV_B_LO,
                     g_VT + (size_t)v0 * N_TOK + (size_t)b * NPER + ch * 128, N_TOK, tid);
        __syncthreads();
        gemm128(c, sb + KV_A_HI, sb + KV_A_LO, sb + KV_B_HI, sb + KV_B_LO, lane, m0, n0);
    }
    __syncthreads();
    float* dbuf = (float*)smem;   // [128][129], reuses A region
    frag_to_dbuf(dbuf, c, lane, m0, n0);
    __syncthreads();
#pragma unroll 2
    for (int i = 0; i < 64; i++) {
        int f = i * 256 + tid, vv = f >> 7, mm = f & 127;
        g_KVT[((size_t)b * DV + v0 + vv) * MF + m0g + mm] = pack_split(dbuf[mm * 129 + vv]);
    }
}

// ---------------- norm[i] = Qp[i] . Ksum[seg] + eps ----------------
__global__ __launch_bounds__(256)
void norm_kernel()
{
    const int tid = threadIdx.x, ty = tid >> 5, tx = tid & 31;
    const int row = blockIdx.x * 8 + ty;
    const int b = row >> 9;
    const float* P = g_KsumP + (size_t)(4 * b) * 256;
    float dot = 0.f;
#pragma unroll
    for (int half = 0; half < 2; half++) {
        int c0 = half * 128 + tx * 4;
        uint4 q = *(const uint4*)&g_Qp[(size_t)row * MF + c0];
        float k0 = P[c0] + P[256 + c0] + P[512 + c0] + P[768 + c0];
        float k1 = P[c0 + 1] + P[256 + c0 + 1] + P[512 + c0 + 1] + P[768 + c0 + 1];
        float k2 = P[c0 + 2] + P[256 + c0 + 2] + P[512 + c0 + 2] + P[768 + c0 + 2];
        float k3 = P[c0 + 3] + P[256 + c0 + 3] + P[512 + c0 + 3] + P[768 + c0 + 3];
        dot += unpack_val(q.x) * k0 + unpack_val(q.y) * k1
             + unpack_val(q.z) * k2 + unpack_val(q.w) * k3;
    }
    dot = warpSum(dot);
    if (tx == 0) g_norm[row] = dot + EPS_NORM;
}

// ---------------- out: D[row=128][v=128] = Qp @ KVT^T, /norm ----------------
__global__ __launch_bounds__(256, 1)
void out_kernel(float* __restrict__ Out)
{
    extern __shared__ char smem[];
    const uint32_t sb = smem_u32(smem);
    const int tid = threadIdx.x, wid = tid >> 5, lane = tid & 31;
    const int b = blockIdx.x >> 3, rt = (blockIdx.x >> 1) & 3, vt = blockIdx.x & 1;
    const int row0 = b * NPER + rt * 128, v0 = vt * 128;
    const int m0 = (wid & 3) * 32, n0 = (wid >> 2) * 64;
    float* nrm_sm = (float*)(smem + 139264);   // [128]

    float c[2][8][4];
#pragma unroll
    for (int mt = 0; mt < 2; mt++)
#pragma unroll
        for (int nt = 0; nt < 8; nt++)
#pragma unroll
            for (int q = 0; q < 4; q++) c[mt][nt][q] = 0.f;

    for (int ch = 0; ch < 2; ch++) {
        __syncthreads();
        stage_packed(smem + KV_A_HI, smem + KV_A_LO,
                     g_Qp + (size_t)row0 * MF + ch * 128, MF, tid);
        stage_packed(smem + KV_B_HI, smem + KV_B_LO,
                     g_KVT + ((size_t)b * DV + v0) * MF + ch * 128, MF, tid);
        __syncthreads();
        gemm128(c, sb + KV_A_HI, sb + KV_A_LO, sb + KV_B_HI, sb + KV_B_LO, lane, m0, n0);
    }
    __syncthreads();
    float* dbuf = (float*)smem;   // [128][129]
    frag_to_dbuf(dbuf, c, lane, m0, n0);
    if (tid < 128) nrm_sm[tid] = 1.0f / g_norm[row0 + tid];
    __syncthreads();
#pragma unroll 2
    for (int i = 0; i < 64; i++) {
        int f = i * 256 + tid, rr = f >> 7, cc = f & 127;
        Out[(size_t)(row0 + rr) * DV + v0 + cc] = dbuf[rr * 129 + cc] * nrm_sm[rr];
    }
}

// ---------------- launch ----------------
#define SCL_SMEM  132608
#define OMT_SMEM  131584
#define VT_SMEM   66048

extern "C" void kernel_launch(void* const* d_in, const int* in_sizes, int n_in,
                              void* d_out, int out_size)
{
    (void)in_sizes; (void)n_in; (void)out_size;
    const float* Q     = (const float*)d_in[0];
    const float* K     = (const float*)d_in[1];
    const float* V     = (const float*)d_in[2];
    const float* omega = (const float*)d_in[3];
    float* Out = (float*)d_out;

    cudaFuncSetAttribute(omT_kernel,     cudaFuncAttributeMaxDynamicSharedMemorySize, OMT_SMEM);
    cudaFuncSetAttribute(vT_kernel,      cudaFuncAttributeMaxDynamicSharedMemorySize, VT_SMEM);
    cudaFuncSetAttribute(phi_kernel<1>,  cudaFuncAttributeMaxDynamicSharedMemorySize, PHI_SMEM);
    cudaFuncSetAttribute(phi_kernel<0>,  cudaFuncAttributeMaxDynamicSharedMemorySize, PHI_SMEM);
    cudaFuncSetAttribute(scalekT_kernel, cudaFuncAttributeMaxDynamicSharedMemorySize, SCL_SMEM);
    cudaFuncSetAttribute(kv_kernel,      cudaFuncAttributeMaxDynamicSharedMemorySize, KV_SMEM);
    cudaFuncSetAttribute(out_kernel,     cudaFuncAttributeMaxDynamicSharedMemorySize, KV_SMEM);

    init_kernel<<<1, 64>>>();
    omT_kernel<<<1, 256, OMT_SMEM>>>(omega);
    vT_kernel<<<dim3(256, 2), 256, VT_SMEM>>>(V);
    phi_kernel<1><<<256, 256, PHI_SMEM>>>(Q);
    phi_kernel<0><<<256, 256, PHI_SMEM>>>(K);
    scalekT_kernel<<<256, 256, SCL_SMEM>>>();
    kv_kernel<<<256, 256, KV_SMEM>>>();
    norm_kernel<<<N_TOK / 8, 256>>>();
    out_kernel<<<512, 256, KV_SMEM>>>(Out);
}

// round 5
// speedup vs baseline: 1.5408x; 1.3227x over previous
#include <cuda_runtime.h>
#include <cuda_bf16.h>
#include <cstdint>

#define N_TOK   32768
#define NBATCH  64
#define NPER    512
#define DQK     128
#define MF      256
#define DV      256
#define PAD     136   /* bf16 row stride in smem: conflict-free ldmatrix */

#define INV_D4      0.29730177875068026f
#define INV_SQRT_M  0.0625f
#define EPS_PHI     1e-4f
#define EPS_NORM    1e-8f

// ---------------- scratch: separate hi/lo bf16 planes ----------------
__device__ uint16_t g_QpH [(size_t)N_TOK * MF], g_QpL [(size_t)N_TOK * MF];
__device__ uint16_t g_Kp0H[(size_t)N_TOK * MF], g_Kp0L[(size_t)N_TOK * MF];
__device__ uint16_t g_KpTH[(size_t)MF * N_TOK], g_KpTL[(size_t)MF * N_TOK];
__device__ uint16_t g_VTH [(size_t)DV * N_TOK], g_VTL [(size_t)DV * N_TOK];
__device__ uint16_t g_omTH[(size_t)MF * DQK],   g_omTL[(size_t)MF * DQK];
__device__ uint16_t g_KVTH[(size_t)NBATCH * DV * MF], g_KVTL[(size_t)NBATCH * DV * MF];
__device__ float    g_rowmax[N_TOK];
__device__ unsigned g_segmax[NBATCH];
__device__ float    g_KsumP[256 * MF];
__device__ float    g_norm[N_TOK];

// ---------------- helpers ----------------
__device__ __forceinline__ uint32_t smem_u32(const void* p) {
    uint32_t a;
    asm("{ .reg .u64 t; cvta.to.shared.u64 t, %1; cvt.u32.u64 %0, t; }" : "=r"(a) : "l"(p));
    return a;
}
__device__ __forceinline__ void ldsm4(uint32_t* r, uint32_t a) {
    asm volatile("ldmatrix.sync.aligned.m8n8.x4.shared.b16 {%0,%1,%2,%3}, [%4];"
        : "=r"(r[0]), "=r"(r[1]), "=r"(r[2]), "=r"(r[3]) : "r"(a));
}
__device__ __forceinline__ void mma16816(float* c, const uint32_t* a, const uint32_t* b) {
    asm volatile("mma.sync.aligned.m16n8k16.row.col.f32.bf16.bf16.f32 "
        "{%0,%1,%2,%3}, {%4,%5,%6,%7}, {%8,%9}, {%0,%1,%2,%3};"
        : "+f"(c[0]), "+f"(c[1]), "+f"(c[2]), "+f"(c[3])
        : "r"(a[0]), "r"(a[1]), "r"(a[2]), "r"(a[3]), "r"(b[0]), "r"(b[1]));
}
__device__ __forceinline__ void split1(float v, uint16_t& h, uint16_t& l) {
    __nv_bfloat16 hh = __float2bfloat16(v);
    __nv_bfloat16 ll = __float2bfloat16(v - __bfloat162float(hh));
    h = __bfloat16_as_ushort(hh); l = __bfloat16_as_ushort(ll);
}
__device__ __forceinline__ void split_pair(float a, float b, uint32_t& hw, uint32_t& lw) {
    uint16_t h0, l0, h1, l1;
    split1(a, h0, l0); split1(b, h1, l1);
    hw = (uint32_t)h0 | ((uint32_t)h1 << 16);
    lw = (uint32_t)l0 | ((uint32_t)l1 << 16);
}
__device__ __forceinline__ float from2(uint16_t h, uint16_t l) {
    return __bfloat162float(__ushort_as_bfloat16(h)) + __bfloat162float(__ushort_as_bfloat16(l));
}
__device__ __forceinline__ unsigned f2o(float f) {
    unsigned u = __float_as_uint(f);
    return (u & 0x80000000u) ? ~u : (u | 0x80000000u);
}
__device__ __forceinline__ float o2f(unsigned u) {
    return (u & 0x80000000u) ? __uint_as_float(u & 0x7fffffffu) : __uint_as_float(~u);
}
__device__ __forceinline__ float warpSum(float v) {
#pragma unroll
    for (int o = 16; o > 0; o >>= 1) v += __shfl_xor_sync(0xffffffffu, v, o);
    return v;
}
__device__ __forceinline__ float warpMax(float v) {
#pragma unroll
    for (int o = 16; o > 0; o >>= 1) v = fmaxf(v, __shfl_xor_sync(0xffffffffu, v, o));
    return v;
}
#define CP_COMMIT() asm volatile("cp.async.commit_group;" ::: "memory")
#define CP_WAIT0()  asm volatile("cp.async.wait_group 0;" ::: "memory")

// stage ROWS x 128 u16 tile via cp.async (pure copy), smem row stride PAD u16
template <int ROWS>
__device__ __forceinline__ void stage_async(uint32_t sdst, const uint16_t* __restrict__ g,
                                            size_t stride, int tid)
{
#pragma unroll
    for (int i = 0; i < ROWS * 16 / 512; i++) {
        int idx = i * 512 + tid;
        int r = idx >> 4, ck = idx & 15;
        uint32_t sa = sdst + (uint32_t)(r * PAD * 2 + ck * 16);
        const void* ga = (const void*)(g + (size_t)r * stride + ck * 8);
        asm volatile("cp.async.cg.shared.global [%0], [%1], 16;" :: "r"(sa), "l"(ga));
    }
}

// ---------------- warp-tiled bf16x3 GEMM: one K=128 chunk ----------------
// Block 128x256, 16 warps (4m x 4n), warp tile 32x64. C = Ah*Bh + Al*Bh + Ah*Bl.
__device__ __forceinline__ void gemm_chunk(float c[2][8][4],
    uint32_t Ahi, uint32_t Alo, uint32_t Bhi, uint32_t Blo, int lane, int m0, int n0)
{
    const uint32_t ao0 = (uint32_t)((m0 + (lane & 15)) * PAD + (lane >> 4) * 8) * 2u;
    const uint32_t bo0 = (uint32_t)((n0 + ((lane >> 4) << 3) + (lane & 7)) * PAD
                                    + ((lane >> 3) & 1) * 8) * 2u;
#pragma unroll
    for (int ks = 0; ks < 8; ks++) {
        uint32_t ah[2][4], al[2][4];
        ldsm4(ah[0], Ahi + ao0 + ks * 32);
        ldsm4(ah[1], Ahi + ao0 + 16 * PAD * 2 + ks * 32);
        ldsm4(al[0], Alo + ao0 + ks * 32);
        ldsm4(al[1], Alo + ao0 + 16 * PAD * 2 + ks * 32);
#pragma unroll
        for (int n2 = 0; n2 < 4; n2++) {
            uint32_t bh[4], bl[4];
            ldsm4(bh, Bhi + bo0 + n2 * 16 * PAD * 2 + ks * 32);
            ldsm4(bl, Blo + bo0 + n2 * 16 * PAD * 2 + ks * 32);
#pragma unroll
            for (int mt = 0; mt < 2; mt++) {
                mma16816(c[mt][n2 * 2],     ah[mt], &bh[0]);
                mma16816(c[mt][n2 * 2],     al[mt], &bh[0]);
                mma16816(c[mt][n2 * 2],     ah[mt], &bl[0]);
                mma16816(c[mt][n2 * 2 + 1], ah[mt], &bh[2]);
                mma16816(c[mt][n2 * 2 + 1], al[mt], &bh[2]);
                mma16816(c[mt][n2 * 2 + 1], ah[mt], &bl[2]);
            }
        }
    }
}

// fragments -> f32 smem dbuf [128][257]
__device__ __forceinline__ void frag_to_dbuf(float* dbuf, const float c[2][8][4],
                                             int lane, int m0, int n0)
{
    int g = lane >> 2, j = lane & 3;
#pragma unroll
    for (int mt = 0; mt < 2; mt++)
#pragma unroll
        for (int nt = 0; nt < 8; nt++) {
            int r0 = m0 + mt * 16 + g, cc = n0 + nt * 8 + j * 2;
            dbuf[r0 * 257 + cc]           = c[mt][nt][0];
            dbuf[r0 * 257 + cc + 1]       = c[mt][nt][1];
            dbuf[(r0 + 8) * 257 + cc]     = c[mt][nt][2];
            dbuf[(r0 + 8) * 257 + cc + 1] = c[mt][nt][3];
        }
}

// ---------------- init ----------------
__global__ void init_kernel() {
    if (threadIdx.x < NBATCH) g_segmax[threadIdx.x] = 0u;
}

// ---------------- omega^T: [128k][256m] f32 -> omT planes [m][k] ----------------
__global__ __launch_bounds__(256)
void omT_kernel(const float* __restrict__ omega) {
    extern __shared__ char smem[];
    float* tile = (float*)smem;                       // [128][257]
    const int tid = threadIdx.x;
    for (int i = 0; i < 128; i++) {
        int f = i * 256 + tid, k = f >> 8, n = f & 255;
        tile[k * 257 + n] = omega[k * MF + n];
    }
    __syncthreads();
    for (int i = 0; i < 64; i++) {
        int f = i * 256 + tid, m = f >> 6, k2 = (f & 63) * 2;
        uint32_t hw, lw;
        split_pair(tile[k2 * 257 + m], tile[(k2 + 1) * 257 + m], hw, lw);
        *(uint32_t*)&g_omTH[m * DQK + k2] = hw;
        *(uint32_t*)&g_omTL[m * DQK + k2] = lw;
    }
}

// ---------------- V^T: tiles [128n][128v] -> VT planes [v][n] ----------------
__global__ __launch_bounds__(256)
void vT_kernel(const float* __restrict__ V) {
    extern __shared__ char smem[];
    float* tile = (float*)smem;                       // [128][129]
    const int tid = threadIdx.x;
    const int n0 = blockIdx.x * 128, v0 = blockIdx.y * 128;
    for (int i = 0; i < 64; i++) {
        int f = i * 256 + tid, n = f >> 7, v = f & 127;
        tile[n * 129 + v] = V[(size_t)(n0 + n) * DV + v0 + v];
    }
    __syncthreads();
    for (int i = 0; i < 32; i++) {
        int f = i * 256 + tid, v = f >> 6, n2 = (f & 63) * 2;
        uint32_t hw, lw;
        split_pair(tile[n2 * 129 + v], tile[(n2 + 1) * 129 + v], hw, lw);
        *(uint32_t*)&g_VTH[(size_t)(v0 + v) * N_TOK + n0 + n2] = hw;
        *(uint32_t*)&g_VTL[(size_t)(v0 + v) * N_TOK + n0 + n2] = lw;
    }
}

// ---------------- phi: HMMA bf16x3 + h + rowmax + exp, single N=256 pass ----------------
#define PHI_A_HI  4096
#define PHI_A_LO  (PHI_A_HI + 34816)
#define PHI_B_HI  (PHI_A_LO + 34816)
#define PHI_B_LO  (PHI_B_HI + 69632)
#define PHI_SMEM  (PHI_B_LO + 69632)

template <int ISQ>
__global__ __launch_bounds__(512, 1)
void phi_kernel(const float* __restrict__ X)
{
    extern __shared__ char smem[];
    const uint32_t sb = smem_u32(smem);
    const int tid = threadIdx.x, wid = tid >> 5, lane = tid & 31;
    const int row0 = blockIdx.x * 128;
    const int m0 = (wid & 3) * 32, n0 = (wid >> 2) * 64, warpN = wid >> 2;

    float* h_sm    = (float*)smem;               // [128]
    float* rmax_sm = (float*)(smem + 512);       // [128]
    float* rmaxp   = (float*)(smem + 1024);      // [128][4]
    float* wm_sm   = (float*)(smem + 3072);      // [4]

    // async-stage omega^T planes (B: 256 x 128)
    stage_async<256>(sb + PHI_B_HI, g_omTH, DQK, tid);
    stage_async<256>(sb + PHI_B_LO, g_omTL, DQK, tid);
    CP_COMMIT();

    // A: load X, scale, h per row, split hi/lo (compute path)
#pragma unroll
    for (int i = 0; i < 8; i++) {
        int row = i * 16 + wid;
        float4 v = ((const float4*)(X + (size_t)(row0 + row) * DQK))[lane];
        v.x *= INV_D4; v.y *= INV_D4; v.z *= INV_D4; v.w *= INV_D4;
        float hs = warpSum(v.x * v.x + v.y * v.y + v.z * v.z + v.w * v.w);
        if (lane == 0) h_sm[row] = 0.5f * hs;
        uint32_t hwA, lwA, hwB, lwB;
        split_pair(v.x, v.y, hwA, lwA);
        split_pair(v.z, v.w, hwB, lwB);
        uint32_t off = (uint32_t)(row * PAD + lane * 4) * 2u;
        *(uint2*)(smem + PHI_A_HI + off) = make_uint2(hwA, hwB);
        *(uint2*)(smem + PHI_A_LO + off) = make_uint2(lwA, lwB);
    }
    CP_WAIT0();
    __syncthreads();

    float c[2][8][4];
#pragma unroll
    for (int mt = 0; mt < 2; mt++)
#pragma unroll
        for (int nt = 0; nt < 8; nt++)
#pragma unroll
            for (int q = 0; q < 4; q++) c[mt][nt][q] = 0.f;
    gemm_chunk(c, sb + PHI_A_HI, sb + PHI_A_LO, sb + PHI_B_HI, sb + PHI_B_LO, lane, m0, n0);

    // rowmax from fragments
    float rmx[2][2] = {{-3.0e38f, -3.0e38f}, {-3.0e38f, -3.0e38f}};
#pragma unroll
    for (int mt = 0; mt < 2; mt++)
#pragma unroll
        for (int nt = 0; nt < 8; nt++) {
            rmx[mt][0] = fmaxf(rmx[mt][0], fmaxf(c[mt][nt][0], c[mt][nt][1]));
            rmx[mt][1] = fmaxf(rmx[mt][1], fmaxf(c[mt][nt][2], c[mt][nt][3]));
        }
#pragma unroll
    for (int mt = 0; mt < 2; mt++)
#pragma unroll
        for (int hh = 0; hh < 2; hh++) {
            float v = rmx[mt][hh];
            v = fmaxf(v, __shfl_xor_sync(0xffffffffu, v, 1));
            v = fmaxf(v, __shfl_xor_sync(0xffffffffu, v, 2));
            rmx[mt][hh] = v;
        }
    {
        int g = lane >> 2;
        if ((lane & 3) == 0) {
            rmaxp[(m0 + g) * 4 + warpN]      = rmx[0][0];
            rmaxp[(m0 + g + 8) * 4 + warpN]  = rmx[0][1];
            rmaxp[(m0 + 16 + g) * 4 + warpN] = rmx[1][0];
            rmaxp[(m0 + 24 + g) * 4 + warpN] = rmx[1][1];
        }
    }
    __syncthreads();
    if (tid < 128) {
        float rm = fmaxf(fmaxf(rmaxp[tid * 4], rmaxp[tid * 4 + 1]),
                         fmaxf(rmaxp[tid * 4 + 2], rmaxp[tid * 4 + 3]));
        rmax_sm[tid] = rm;
        if (!ISQ) {
            g_rowmax[row0 + tid] = rm;
            float bm = warpMax(rm);
            if (lane == 0) wm_sm[wid] = bm;
        }
    }
    __syncthreads();

    // epilogue: exp + split, direct plane stores
    uint16_t* dH = ISQ ? g_QpH : g_Kp0H;
    uint16_t* dL = ISQ ? g_QpL : g_Kp0L;
    {
        int g = lane >> 2, j = lane & 3;
#pragma unroll
        for (int mt = 0; mt < 2; mt++) {
            int r0 = m0 + mt * 16 + g, r1 = r0 + 8;
            float hm0 = h_sm[r0] + rmax_sm[r0];
            float hm1 = h_sm[r1] + rmax_sm[r1];
#pragma unroll
            for (int nt = 0; nt < 8; nt++) {
                int col = n0 + nt * 8 + j * 2;
                float v0, v1, v2, v3;
                if (ISQ) {
                    v0 = (__expf(c[mt][nt][0] - hm0) + EPS_PHI) * INV_SQRT_M;
                    v1 = (__expf(c[mt][nt][1] - hm0) + EPS_PHI) * INV_SQRT_M;
                    v2 = (__expf(c[mt][nt][2] - hm1) + EPS_PHI) * INV_SQRT_M;
                    v3 = (__expf(c[mt][nt][3] - hm1) + EPS_PHI) * INV_SQRT_M;
                } else {
                    v0 = __expf(c[mt][nt][0] - hm0);
                    v1 = __expf(c[mt][nt][1] - hm0);
                    v2 = __expf(c[mt][nt][2] - hm1);
                    v3 = __expf(c[mt][nt][3] - hm1);
                }
                uint32_t hw, lw;
                split_pair(v0, v1, hw, lw);
                *(uint32_t*)&dH[(size_t)(row0 + r0) * MF + col] = hw;
                *(uint32_t*)&dL[(size_t)(row0 + r0) * MF + col] = lw;
                split_pair(v2, v3, hw, lw);
                *(uint32_t*)&dH[(size_t)(row0 + r1) * MF + col] = hw;
                *(uint32_t*)&dL[(size_t)(row0 + r1) * MF + col] = lw;
            }
        }
    }
    if (!ISQ && tid == 0) {
        float bm = fmaxf(fmaxf(wm_sm[0], wm_sm[1]), fmaxf(wm_sm[2], wm_sm[3]));
        atomicMax(&g_segmax[row0 >> 9], f2o(bm));
    }
}

// ---------------- scalekT: Kp0 -> KpT planes (rescale+eps+transpose) + Ksum ----------------
__global__ __launch_bounds__(256)
void scalekT_kernel()
{
    extern __shared__ char smem[];
    float* sfac = (float*)smem;                        // [128]
    float* tile = (float*)(smem + 1024);               // [128][257]
    const int tid = threadIdx.x;
    const int nt = blockIdx.x, n0 = nt * 128;
    if (tid < 128) sfac[tid] = __expf(g_rowmax[n0 + tid] - o2f(g_segmax[n0 >> 9]));
#pragma unroll 4
    for (int i = 0; i < 64; i++) {
        int f = i * 256 + tid, n = f >> 7, m2 = (f & 127) * 2;
        uint32_t hw = *(const uint32_t*)&g_Kp0H[(size_t)(n0 + n) * MF + m2];
        uint32_t lw = *(const uint32_t*)&g_Kp0L[(size_t)(n0 + n) * MF + m2];
        tile[n * 257 + m2]     = from2((uint16_t)hw, (uint16_t)lw);
        tile[n * 257 + m2 + 1] = from2((uint16_t)(hw >> 16), (uint16_t)(lw >> 16));
    }
    __syncthreads();
#pragma unroll 4
    for (int i = 0; i < 64; i++) {
        int f = i * 256 + tid, m = f >> 6, n2 = (f & 63) * 2;
        float v0 = (tile[n2 * 257 + m] * sfac[n2] + EPS_PHI) * INV_SQRT_M;
        float v1 = (tile[(n2 + 1) * 257 + m] * sfac[n2 + 1] + EPS_PHI) * INV_SQRT_M;
        uint32_t hw, lw;
        split_pair(v0, v1, hw, lw);
        *(uint32_t*)&g_KpTH[(size_t)m * N_TOK + n0 + n2] = hw;
        *(uint32_t*)&g_KpTL[(size_t)m * N_TOK + n0 + n2] = lw;
    }
    float s = 0.f;
#pragma unroll 4
    for (int nn = 0; nn < 128; nn++)
        s += (tile[nn * 257 + tid] * sfac[nn] + EPS_PHI) * INV_SQRT_M;
    g_KsumP[nt * 256 + tid] = s;
}

// ---------------- kv: D[m=128][v=256] = sum_n KpT[m][n]*VT[v][n] ----------------
#define G_A_HI  0
#define G_A_LO  34816
#define G_B_HI  69632
#define G_B_LO  (69632 + 69632)
#define G_SMEM  (G_B_LO + 69632)

__global__ __launch_bounds__(512, 1)
void kv_kernel()
{
    extern __shared__ char smem[];
    const uint32_t sb = smem_u32(smem);
    const int tid = threadIdx.x, wid = tid >> 5, lane = tid & 31;
    const int b = blockIdx.x >> 1, mt_ = blockIdx.x & 1;
    const int m0g = mt_ * 128;
    const int m0 = (wid & 3) * 32, n0 = (wid >> 2) * 64;

    float c[2][8][4];
#pragma unroll
    for (int mt = 0; mt < 2; mt++)
#pragma unroll
        for (int nt = 0; nt < 8; nt++)
#pragma unroll
            for (int q = 0; q < 4; q++) c[mt][nt][q] = 0.f;

    for (int ch = 0; ch < 4; ch++) {
        if (ch) __syncthreads();
        size_t nc = (size_t)b * NPER + ch * 128;
        stage_async<128>(sb + G_A_HI, g_KpTH + (size_t)m0g * N_TOK + nc, N_TOK, tid);
        stage_async<128>(sb + G_A_LO, g_KpTL + (size_t)m0g * N_TOK + nc, N_TOK, tid);
        stage_async<256>(sb + G_B_HI, g_VTH + nc, N_TOK, tid);
        stage_async<256>(sb + G_B_LO, g_VTL + nc, N_TOK, tid);
        CP_COMMIT(); CP_WAIT0();
        __syncthreads();
        gemm_chunk(c, sb + G_A_HI, sb + G_A_LO, sb + G_B_HI, sb + G_B_LO, lane, m0, n0);
    }
    __syncthreads();
    float* dbuf = (float*)smem;   // [128][257]
    frag_to_dbuf(dbuf, c, lane, m0, n0);
    __syncthreads();
#pragma unroll
    for (int i = 0; i < 32; i++) {
        int f = i * 512 + tid, v = f >> 6, p = f & 63;
        uint32_t hw, lw;
        split_pair(dbuf[(2 * p) * 257 + v], dbuf[(2 * p + 1) * 257 + v], hw, lw);
        *(uint32_t*)&g_KVTH[((size_t)b * DV + v) * MF + m0g + 2 * p] = hw;
        *(uint32_t*)&g_KVTL[((size_t)b * DV + v) * MF + m0g + 2 * p] = lw;
    }
}

// ---------------- norm[i] = Qp[i] . Ksum[seg] + eps ----------------
__global__ __launch_bounds__(256)
void norm_kernel()
{
    const int tid = threadIdx.x, ty = tid >> 5, tx = tid & 31;
    const int row = blockIdx.x * 8 + ty;
    const int b = row >> 9;
    const float* P = g_KsumP + (size_t)(4 * b) * 256;
    float dot = 0.f;
#pragma unroll
    for (int half = 0; half < 2; half++) {
        int c0 = half * 128 + tx * 4;
        uint2 hq = *(const uint2*)&g_QpH[(size_t)row * MF + c0];
        uint2 lq = *(const uint2*)&g_QpL[(size_t)row * MF + c0];
        float q0 = from2((uint16_t)hq.x, (uint16_t)lq.x);
        float q1 = from2((uint16_t)(hq.x >> 16), (uint16_t)(lq.x >> 16));
        float q2 = from2((uint16_t)hq.y, (uint16_t)lq.y);
        float q3 = from2((uint16_t)(hq.y >> 16), (uint16_t)(lq.y >> 16));
        float k0 = P[c0] + P[256 + c0] + P[512 + c0] + P[768 + c0];
        float k1 = P[c0 + 1] + P[256 + c0 + 1] + P[512 + c0 + 1] + P[768 + c0 + 1];
        float k2 = P[c0 + 2] + P[256 + c0 + 2] + P[512 + c0 + 2] + P[768 + c0 + 2];
        float k3 = P[c0 + 3] + P[256 + c0 + 3] + P[512 + c0 + 3] + P[768 + c0 + 3];
        dot += q0 * k0 + q1 * k1 + q2 * k2 + q3 * k3;
    }
    dot = warpSum(dot);
    if (tx == 0) g_norm[row] = dot + EPS_NORM;
}

// ---------------- out: D[row=128][v=256] = Qp @ KVT^T, /norm ----------------
__global__ __launch_bounds__(512, 1)
void out_kernel(float* __restrict__ Out)
{
    extern __shared__ char smem[];
    const uint32_t sb = smem_u32(smem);
    const int tid = threadIdx.x, wid = tid >> 5, lane = tid & 31;
    const int b = blockIdx.x >> 2, rt = blockIdx.x & 3;
    const int row0 = b * NPER + rt * 128;
    const int m0 = (wid & 3) * 32, n0 = (wid >> 2) * 64;

    float c[2][8][4];
#pragma unroll
    for (int mt = 0; mt < 2; mt++)
#pragma unroll
        for (int nt = 0; nt < 8; nt++)
#pragma unroll
            for (int q = 0; q < 4; q++) c[mt][nt][q] = 0.f;

    for (int ch = 0; ch < 2; ch++) {
        if (ch) __syncthreads();
        stage_async<128>(sb + G_A_HI, g_QpH + (size_t)row0 * MF + ch * 128, MF, tid);
        stage_async<128>(sb + G_A_LO, g_QpL + (size_t)row0 * MF + ch * 128, MF, tid);
        stage_async<256>(sb + G_B_HI, g_KVTH + (size_t)b * DV * MF + ch * 128, MF, tid);
        stage_async<256>(sb + G_B_LO, g_KVTL + (size_t)b * DV * MF + ch * 128, MF, tid);
        CP_COMMIT(); CP_WAIT0();
        __syncthreads();
        gemm_chunk(c, sb + G_A_HI, sb + G_A_LO, sb + G_B_HI, sb + G_B_LO, lane, m0, n0);
    }
    __syncthreads();
    float* dbuf = (float*)smem;                      // [128][257]
    float* nrm_sm = (float*)(smem + 132096);         // [128]
    frag_to_dbuf(dbuf, c, lane, m0, n0);
    if (tid < 128) nrm_sm[tid] = 1.0f / g_norm[row0 + tid];
    __syncthreads();
#pragma unroll
    for (int i = 0; i < 16; i++) {
        int f = i * 512 + tid, rr = f >> 6, c4 = (f & 63) * 4;
        float inv = nrm_sm[rr];
        float4 o = make_float4(dbuf[rr * 257 + c4] * inv, dbuf[rr * 257 + c4 + 1] * inv,
                               dbuf[rr * 257 + c4 + 2] * inv, dbuf[rr * 257 + c4 + 3] * inv);
        *(float4*)(Out + (size_t)(row0 + rr) * DV + c4) = o;
    }
}

// ---------------- launch ----------------
#define SCL_SMEM  132608
#define OMT_SMEM  131584
#define VT_SMEM   66048

extern "C" void kernel_launch(void* const* d_in, const int* in_sizes, int n_in,
                              void* d_out, int out_size)
{
    (void)in_sizes; (void)n_in; (void)out_size;
    const float* Q     = (const float*)d_in[0];
    const float* K     = (const float*)d_in[1];
    const float* V     = (const float*)d_in[2];
    const float* omega = (const float*)d_in[3];
    float* Out = (float*)d_out;

    cudaFuncSetAttribute(omT_kernel,     cudaFuncAttributeMaxDynamicSharedMemorySize, OMT_SMEM);
    cudaFuncSetAttribute(vT_kernel,      cudaFuncAttributeMaxDynamicSharedMemorySize, VT_SMEM);
    cudaFuncSetAttribute(phi_kernel<1>,  cudaFuncAttributeMaxDynamicSharedMemorySize, PHI_SMEM);
    cudaFuncSetAttribute(phi_kernel<0>,  cudaFuncAttributeMaxDynamicSharedMemorySize, PHI_SMEM);
    cudaFuncSetAttribute(scalekT_kernel, cudaFuncAttributeMaxDynamicSharedMemorySize, SCL_SMEM);
    cudaFuncSetAttribute(kv_kernel,      cudaFuncAttributeMaxDynamicSharedMemorySize, G_SMEM);
    cudaFuncSetAttribute(out_kernel,     cudaFuncAttributeMaxDynamicSharedMemorySize, G_SMEM);

    init_kernel<<<1, 64>>>();
    omT_kernel<<<1, 256, OMT_SMEM>>>(omega);
    vT_kernel<<<dim3(256, 2), 256, VT_SMEM>>>(V);
    phi_kernel<1><<<256, 512, PHI_SMEM>>>(Q);
    phi_kernel<0><<<256, 512, PHI_SMEM>>>(K);
    scalekT_kernel<<<256, 256, SCL_SMEM>>>();
    kv_kernel<<<128, 512, G_SMEM>>>();
    norm_kernel<<<N_TOK / 8, 256>>>();
    out_kernel<<<256, 512, G_SMEM>>>(Out);
}

// round 6
// speedup vs baseline: 1.7698x; 1.1486x over previous
#include <cuda_runtime.h>
#include <cuda_bf16.h>
#include <cstdint>

#define N_TOK   32768
#define NBATCH  64
#define NPER    512
#define DQK     128
#define MF      256
#define DV      256
#define PAD     136   /* bf16 row stride for 128-col tiles */
#define PAD64   72    /* bf16 row stride for 64-col tiles */

#define INV_D4      0.29730177875068026f
#define INV_SQRT_M  0.0625f
#define EPS_PHI     1e-4f
#define EPS_NORM    1e-8f

// ---------------- scratch ----------------
__device__ uint16_t g_QpH [(size_t)N_TOK * MF], g_QpL [(size_t)N_TOK * MF];   // [tok][feat]
__device__ uint16_t g_KpTH[(size_t)MF * N_TOK], g_KpTL[(size_t)MF * N_TOK];   // Kp0^T [feat][tok]
__device__ uint16_t g_VTH [(size_t)DV * N_TOK], g_VTL [(size_t)DV * N_TOK];   // (s*V)^T [v][tok]
__device__ uint16_t g_omTH[(size_t)MF * DQK],   g_omTL[(size_t)MF * DQK];
__device__ uint16_t g_KVTH[(size_t)NBATCH * DV * MF], g_KVTL[(size_t)NBATCH * DV * MF];
__device__ float    g_rowmax[N_TOK];
__device__ float    g_bmax[256];                 // per 128-token tile
__device__ unsigned g_segmax[NBATCH];
__device__ float    g_W  [256 * MF];             // weighted Kp0 colsum per tile
__device__ float    g_SVp[256 * DV];             // unweighted V colsum per tile
__device__ float    g_norm[N_TOK];

// ---------------- helpers ----------------
__device__ __forceinline__ uint32_t smem_u32(const void* p) {
    uint32_t a;
    asm("{ .reg .u64 t; cvta.to.shared.u64 t, %1; cvt.u32.u64 %0, t; }" : "=r"(a) : "l"(p));
    return a;
}
__device__ __forceinline__ void ldsm4(uint32_t* r, uint32_t a) {
    asm volatile("ldmatrix.sync.aligned.m8n8.x4.shared.b16 {%0,%1,%2,%3}, [%4];"
        : "=r"(r[0]), "=r"(r[1]), "=r"(r[2]), "=r"(r[3]) : "r"(a));
}
__device__ __forceinline__ void mma16816(float* c, const uint32_t* a, const uint32_t* b) {
    asm volatile("mma.sync.aligned.m16n8k16.row.col.f32.bf16.bf16.f32 "
        "{%0,%1,%2,%3}, {%4,%5,%6,%7}, {%8,%9}, {%0,%1,%2,%3};"
        : "+f"(c[0]), "+f"(c[1]), "+f"(c[2]), "+f"(c[3])
        : "r"(a[0]), "r"(a[1]), "r"(a[2]), "r"(a[3]), "r"(b[0]), "r"(b[1]));
}
__device__ __forceinline__ void split1(float v, uint16_t& h, uint16_t& l) {
    __nv_bfloat16 hh = __float2bfloat16(v);
    __nv_bfloat16 ll = __float2bfloat16(v - __bfloat162float(hh));
    h = __bfloat16_as_ushort(hh); l = __bfloat16_as_ushort(ll);
}
__device__ __forceinline__ void split_pair(float a, float b, uint32_t& hw, uint32_t& lw) {
    uint16_t h0, l0, h1, l1;
    split1(a, h0, l0); split1(b, h1, l1);
    hw = (uint32_t)h0 | ((uint32_t)h1 << 16);
    lw = (uint32_t)l0 | ((uint32_t)l1 << 16);
}
__device__ __forceinline__ float from2(uint16_t h, uint16_t l) {
    return __bfloat162float(__ushort_as_bfloat16(h)) + __bfloat162float(__ushort_as_bfloat16(l));
}
__device__ __forceinline__ unsigned f2o(float f) {
    unsigned u = __float_as_uint(f);
    return (u & 0x80000000u) ? ~u : (u | 0x80000000u);
}
__device__ __forceinline__ float o2f(unsigned u) {
    return (u & 0x80000000u) ? __uint_as_float(u & 0x7fffffffu) : __uint_as_float(~u);
}
__device__ __forceinline__ float warpSum(float v) {
#pragma unroll
    for (int o = 16; o > 0; o >>= 1) v += __shfl_xor_sync(0xffffffffu, v, o);
    return v;
}
__device__ __forceinline__ float warpMax(float v) {
#pragma unroll
    for (int o = 16; o > 0; o >>= 1) v = fmaxf(v, __shfl_xor_sync(0xffffffffu, v, o));
    return v;
}
#define CP_COMMIT() asm volatile("cp.async.commit_group;" ::: "memory")
#define CP_WAIT0()  asm volatile("cp.async.wait_group 0;" ::: "memory")
#define CP_WAIT1()  asm volatile("cp.async.wait_group 1;" ::: "memory")

// stage ROWS x COLS u16 tile via cp.async, smem row stride SPAD u16 (512 threads)
template <int ROWS, int COLS, int SPAD>
__device__ __forceinline__ void stage_async(uint32_t sdst, const uint16_t* __restrict__ g,
                                            size_t stride, int tid)
{
    constexpr int CPR = COLS / 8;
    constexpr int ITER = ROWS * CPR / 512;
#pragma unroll
    for (int i = 0; i < ITER; i++) {
        int idx = i * 512 + tid;
        int r = idx / CPR, ck = idx % CPR;
        uint32_t sa = sdst + (uint32_t)(r * SPAD * 2 + ck * 16);
        const void* ga = (const void*)(g + (size_t)r * stride + ck * 8);
        asm volatile("cp.async.cg.shared.global [%0], [%1], 16;" :: "r"(sa), "l"(ga));
    }
}

// ---------------- warp-tiled bf16x3 GEMM: one K-chunk (NKS*16 cols) ----------------
// Block 128x256, 16 warps (4m x 4n), warp tile 32x64. C = Ah*Bh + Al*Bh + Ah*Bl.
template <int NKS, int SPAD>
__device__ __forceinline__ void gemm_chunk(float c[2][8][4],
    uint32_t Ahi, uint32_t Alo, uint32_t Bhi, uint32_t Blo, int lane, int m0, int n0)
{
    const uint32_t ao0 = (uint32_t)((m0 + (lane & 15)) * SPAD + (lane >> 4) * 8) * 2u;
    const uint32_t bo0 = (uint32_t)((n0 + ((lane >> 4) << 3) + (lane & 7)) * SPAD
                                    + ((lane >> 3) & 1) * 8) * 2u;
#pragma unroll
    for (int ks = 0; ks < NKS; ks++) {
        uint32_t ah[2][4], al[2][4];
        ldsm4(ah[0], Ahi + ao0 + ks * 32);
        ldsm4(ah[1], Ahi + ao0 + 16 * SPAD * 2 + ks * 32);
        ldsm4(al[0], Alo + ao0 + ks * 32);
        ldsm4(al[1], Alo + ao0 + 16 * SPAD * 2 + ks * 32);
#pragma unroll
        for (int n2 = 0; n2 < 4; n2++) {
            uint32_t bh[4], bl[4];
            ldsm4(bh, Bhi + bo0 + n2 * 16 * SPAD * 2 + ks * 32);
            ldsm4(bl, Blo + bo0 + n2 * 16 * SPAD * 2 + ks * 32);
#pragma unroll
            for (int mt = 0; mt < 2; mt++) {
                mma16816(c[mt][n2 * 2],     ah[mt], &bh[0]);
                mma16816(c[mt][n2 * 2],     al[mt], &bh[0]);
                mma16816(c[mt][n2 * 2],     ah[mt], &bl[0]);
                mma16816(c[mt][n2 * 2 + 1], ah[mt], &bh[2]);
                mma16816(c[mt][n2 * 2 + 1], al[mt], &bh[2]);
                mma16816(c[mt][n2 * 2 + 1], ah[mt], &bl[2]);
            }
        }
    }
}

// fragments -> f32 smem dbuf [128][257]
__device__ __forceinline__ void frag_to_dbuf(float* dbuf, const float c[2][8][4],
                                             int lane, int m0, int n0)
{
    int g = lane >> 2, j = lane & 3;
#pragma unroll
    for (int mt = 0; mt < 2; mt++)
#pragma unroll
        for (int nt = 0; nt < 8; nt++) {
            int r0 = m0 + mt * 16 + g, cc = n0 + nt * 8 + j * 2;
            dbuf[r0 * 257 + cc]           = c[mt][nt][0];
            dbuf[r0 * 257 + cc + 1]       = c[mt][nt][1];
            dbuf[(r0 + 8) * 257 + cc]     = c[mt][nt][2];
            dbuf[(r0 + 8) * 257 + cc + 1] = c[mt][nt][3];
        }
}

// ---------------- init ----------------
__global__ void init_kernel() {
    if (threadIdx.x < NBATCH) g_segmax[threadIdx.x] = 0u;
}

// ---------------- omega^T: [128k][256m] f32 -> omT planes [m][k] ----------------
__global__ __launch_bounds__(256)
void omT_kernel(const float* __restrict__ omega) {
    extern __shared__ char smem[];
    float* tile = (float*)smem;                       // [128][257]
    const int tid = threadIdx.x;
    for (int i = 0; i < 128; i++) {
        int f = i * 256 + tid, k = f >> 8, n = f & 255;
        tile[k * 257 + n] = omega[k * MF + n];
    }
    __syncthreads();
    for (int i = 0; i < 64; i++) {
        int f = i * 256 + tid, m = f >> 6, k2 = (f & 63) * 2;
        uint32_t hw, lw;
        split_pair(tile[k2 * 257 + m], tile[(k2 + 1) * 257 + m], hw, lw);
        *(uint32_t*)&g_omTH[m * DQK + k2] = hw;
        *(uint32_t*)&g_omTL[m * DQK + k2] = lw;
    }
}

// ---------------- vT: (s*V)^T planes + unweighted V colsum partials ----------------
__global__ __launch_bounds__(256)
void vT_kernel(const float* __restrict__ V) {
    extern __shared__ char smem[];
    float* tile = (float*)smem;                       // [128][129]
    float* s_sm = (float*)(smem + 128 * 129 * 4);     // [128]
    const int tid = threadIdx.x;
    const int nt = blockIdx.x, n0 = nt * 128, v0 = blockIdx.y * 128;
    if (tid < 128) s_sm[tid] = __expf(g_rowmax[n0 + tid] - o2f(g_segmax[n0 >> 9]));
    for (int i = 0; i < 64; i++) {
        int f = i * 256 + tid, n = f >> 7, v = f & 127;
        tile[n * 129 + v] = V[(size_t)(n0 + n) * DV + v0 + v];
    }
    __syncthreads();
    for (int i = 0; i < 32; i++) {
        int f = i * 256 + tid, v = f >> 6, np = (f & 63) * 2;
        uint32_t hw, lw;
        split_pair(tile[np * 129 + v] * s_sm[np],
                   tile[(np + 1) * 129 + v] * s_sm[np + 1], hw, lw);
        *(uint32_t*)&g_VTH[(size_t)(v0 + v) * N_TOK + n0 + np] = hw;
        *(uint32_t*)&g_VTL[(size_t)(v0 + v) * N_TOK + n0 + np] = lw;
    }
    if (tid < 128) {
        float s = 0.f;
#pragma unroll 4
        for (int n = 0; n < 128; n++) s += tile[n * 129 + tid];
        g_SVp[nt * 256 + v0 + tid] = s;
    }
}

// ---------------- phi: HMMA bf16x3 + h + rowmax + exp ----------------
#define PHI_A_HI  4096
#define PHI_A_LO  (PHI_A_HI + 34816)
#define PHI_B_HI  (PHI_A_LO + 34816)
#define PHI_B_LO  (PHI_B_HI + 69632)
#define PHI_SMEM  (PHI_B_LO + 69632)

template <int ISQ>
__global__ __launch_bounds__(512, 1)
void phi_kernel(const float* __restrict__ X)
{
    extern __shared__ char smem[];
    const uint32_t sb = smem_u32(smem);
    const int tid = threadIdx.x, wid = tid >> 5, lane = tid & 31;
    const int row0 = blockIdx.x * 128;
    const int m0 = (wid & 3) * 32, n0 = (wid >> 2) * 64, warpN = wid >> 2;

    float* h_sm    = (float*)smem;               // [128]
    float* rmax_sm = (float*)(smem + 512);       // [128]
    float* rmaxp   = (float*)(smem + 1024);      // [128][4]
    float* wm_sm   = (float*)(smem + 3072);      // [4]
    float* bmax_s  = (float*)(smem + 3088);      // [1]
    float* w_sm    = (float*)(smem + 3200);      // [128]
    float* dbuf    = (float*)(smem + PHI_A_HI);  // [128][257] (reuses A/B after gemm)

    stage_async<256, 128, PAD>(sb + PHI_B_HI, g_omTH, DQK, tid);
    stage_async<256, 128, PAD>(sb + PHI_B_LO, g_omTL, DQK, tid);
    CP_COMMIT();

    // A: load X, scale, h per row, split hi/lo
#pragma unroll
    for (int i = 0; i < 8; i++) {
        int row = i * 16 + wid;
        float4 v = ((const float4*)(X + (size_t)(row0 + row) * DQK))[lane];
        v.x *= INV_D4; v.y *= INV_D4; v.z *= INV_D4; v.w *= INV_D4;
        float hs = warpSum(v.x * v.x + v.y * v.y + v.z * v.z + v.w * v.w);
        if (lane == 0) h_sm[row] = 0.5f * hs;
        uint32_t hwA, lwA, hwB, lwB;
        split_pair(v.x, v.y, hwA, lwA);
        split_pair(v.z, v.w, hwB, lwB);
        uint32_t off = (uint32_t)(row * PAD + lane * 4) * 2u;
        *(uint2*)(smem + PHI_A_HI + off) = make_uint2(hwA, hwB);
        *(uint2*)(smem + PHI_A_LO + off) = make_uint2(lwA, lwB);
    }
    CP_WAIT0();
    __syncthreads();

    float c[2][8][4];
#pragma unroll
    for (int mt = 0; mt < 2; mt++)
#pragma unroll
        for (int nt = 0; nt < 8; nt++)
#pragma unroll
            for (int q = 0; q < 4; q++) c[mt][nt][q] = 0.f;
    gemm_chunk<8, PAD>(c, sb + PHI_A_HI, sb + PHI_A_LO, sb + PHI_B_HI, sb + PHI_B_LO,
                       lane, m0, n0);

    // rowmax from fragments
    float rmx[2][2] = {{-3.0e38f, -3.0e38f}, {-3.0e38f, -3.0e38f}};
#pragma unroll
    for (int mt = 0; mt < 2; mt++)
#pragma unroll
        for (int nt = 0; nt < 8; nt++) {
            rmx[mt][0] = fmaxf(rmx[mt][0], fmaxf(c[mt][nt][0], c[mt][nt][1]));
            rmx[mt][1] = fmaxf(rmx[mt][1], fmaxf(c[mt][nt][2], c[mt][nt][3]));
        }
#pragma unroll
    for (int mt = 0; mt < 2; mt++)
#pragma unroll
        for (int hh = 0; hh < 2; hh++) {
            float v = rmx[mt][hh];
            v = fmaxf(v, __shfl_xor_sync(0xffffffffu, v, 1));
            v = fmaxf(v, __shfl_xor_sync(0xffffffffu, v, 2));
            rmx[mt][hh] = v;
        }
    {
        int g = lane >> 2;
        if ((lane & 3) == 0) {
            rmaxp[(m0 + g) * 4 + warpN]      = rmx[0][0];
            rmaxp[(m0 + g + 8) * 4 + warpN]  = rmx[0][1];
            rmaxp[(m0 + 16 + g) * 4 + warpN] = rmx[1][0];
            rmaxp[(m0 + 24 + g) * 4 + warpN] = rmx[1][1];
        }
    }
    __syncthreads();
    if (tid < 128) {
        float rm = fmaxf(fmaxf(rmaxp[tid * 4], rmaxp[tid * 4 + 1]),
                         fmaxf(rmaxp[tid * 4 + 2], rmaxp[tid * 4 + 3]));
        rmax_sm[tid] = rm;
        if (!ISQ) {
            g_rowmax[row0 + tid] = rm;
            float bm = warpMax(rm);
            if (lane == 0) wm_sm[wid] = bm;
        }
    }
    __syncthreads();
    if (!ISQ) {
        if (tid == 0) {
            float bm = fmaxf(fmaxf(wm_sm[0], wm_sm[1]), fmaxf(wm_sm[2], wm_sm[3]));
            bmax_s[0] = bm;
            g_bmax[blockIdx.x] = bm;
            atomicMax(&g_segmax[row0 >> 9], f2o(bm));
        }
        __syncthreads();
        if (tid < 128) w_sm[tid] = __expf(rmax_sm[tid] - bmax_s[0]);
    }

    if (ISQ) {
        // Qp: exp + eps + scale, direct plane stores [tok][feat]
        int g = lane >> 2, j = lane & 3;
#pragma unroll
        for (int mt = 0; mt < 2; mt++) {
            int r0 = m0 + mt * 16 + g, r1 = r0 + 8;
            float hm0 = h_sm[r0] + rmax_sm[r0];
            float hm1 = h_sm[r1] + rmax_sm[r1];
#pragma unroll
            for (int nt = 0; nt < 8; nt++) {
                int col = n0 + nt * 8 + j * 2;
                float v0 = (__expf(c[mt][nt][0] - hm0) + EPS_PHI) * INV_SQRT_M;
                float v1 = (__expf(c[mt][nt][1] - hm0) + EPS_PHI) * INV_SQRT_M;
                float v2 = (__expf(c[mt][nt][2] - hm1) + EPS_PHI) * INV_SQRT_M;
                float v3 = (__expf(c[mt][nt][3] - hm1) + EPS_PHI) * INV_SQRT_M;
                uint32_t hw, lw;
                split_pair(v0, v1, hw, lw);
                *(uint32_t*)&g_QpH[(size_t)(row0 + r0) * MF + col] = hw;
                *(uint32_t*)&g_QpL[(size_t)(row0 + r0) * MF + col] = lw;
                split_pair(v2, v3, hw, lw);
                *(uint32_t*)&g_QpH[(size_t)(row0 + r1) * MF + col] = hw;
                *(uint32_t*)&g_QpL[(size_t)(row0 + r1) * MF + col] = lw;
            }
        }
    } else {
        // Kp0 = exp(U - h - rowmax) -> dbuf, then transposed plane stores + W partial
        int g = lane >> 2, j = lane & 3;
        float e[2][8][4];
#pragma unroll
        for (int mt = 0; mt < 2; mt++) {
            int r0 = m0 + mt * 16 + g, r1 = r0 + 8;
            float hm0 = h_sm[r0] + rmax_sm[r0];
            float hm1 = h_sm[r1] + rmax_sm[r1];
#pragma unroll
            for (int nt = 0; nt < 8; nt++) {
                e[mt][nt][0] = __expf(c[mt][nt][0] - hm0);
                e[mt][nt][1] = __expf(c[mt][nt][1] - hm0);
                e[mt][nt][2] = __expf(c[mt][nt][2] - hm1);
                e[mt][nt][3] = __expf(c[mt][nt][3] - hm1);
            }
        }
        __syncthreads();   // A/B smem no longer needed
        frag_to_dbuf(dbuf, e, lane, m0, n0);
        __syncthreads();
        // KpT planes: [feat][tok]
#pragma unroll 4
        for (int i = 0; i < 32; i++) {
            int f = i * 512 + tid, feat = f >> 6, tp = (f & 63) * 2;
            uint32_t hw, lw;
            split_pair(dbuf[tp * 257 + feat], dbuf[(tp + 1) * 257 + feat], hw, lw);
            *(uint32_t*)&g_KpTH[(size_t)feat * N_TOK + row0 + tp] = hw;
            *(uint32_t*)&g_KpTL[(size_t)feat * N_TOK + row0 + tp] = lw;
        }
        // weighted colsum partial: W[feat] = sum_tok Kp0[tok][feat]*w[tok]
        if (tid < 256) {
            float s = 0.f;
#pragma unroll 4
            for (int t = 0; t < 128; t++) s += dbuf[t * 257 + tid] * w_sm[t];
            g_W[blockIdx.x * 256 + tid] = s;
        }
    }
}

// ---------------- kv: D[m=128][v=256] = sum_n KpT[m][n]*(sV)T[v][n], pipelined ----------------
#define ST_AH  0
#define ST_AL  18432
#define ST_BH  36864
#define ST_BL  73728
#define ST_SZ  110592
#define PIPE_SMEM (2 * ST_SZ)

__global__ __launch_bounds__(512, 1)
void kv_kernel()
{
    extern __shared__ char smem[];
    const uint32_t sb = smem_u32(smem);
    const int tid = threadIdx.x, wid = tid >> 5, lane = tid & 31;
    const int b = blockIdx.x >> 1, mt_ = blockIdx.x & 1;
    const int m0g = mt_ * 128;
    const int m0 = (wid & 3) * 32, n0 = (wid >> 2) * 64;
    const size_t nb = (size_t)b * NPER;

    float c[2][8][4];
#pragma unroll
    for (int mt = 0; mt < 2; mt++)
#pragma unroll
        for (int nt = 0; nt < 8; nt++)
#pragma unroll
            for (int q = 0; q < 4; q++) c[mt][nt][q] = 0.f;

    // prologue: stage chunk 0
    {
        uint32_t s0 = sb;
        stage_async<128, 64, PAD64>(s0 + ST_AH, g_KpTH + (size_t)m0g * N_TOK + nb, N_TOK, tid);
        stage_async<128, 64, PAD64>(s0 + ST_AL, g_KpTL + (size_t)m0g * N_TOK + nb, N_TOK, tid);
        stage_async<256, 64, PAD64>(s0 + ST_BH, g_VTH + nb, N_TOK, tid);
        stage_async<256, 64, PAD64>(s0 + ST_BL, g_VTL + nb, N_TOK, tid);
        CP_COMMIT();
    }
    for (int ch = 0; ch < 8; ch++) {
        if (ch < 7) {
            uint32_t s1 = sb + ((ch + 1) & 1) * ST_SZ;
            size_t nc = nb + (ch + 1) * 64;
            stage_async<128, 64, PAD64>(s1 + ST_AH, g_KpTH + (size_t)m0g * N_TOK + nc, N_TOK, tid);
            stage_async<128, 64, PAD64>(s1 + ST_AL, g_KpTL + (size_t)m0g * N_TOK + nc, N_TOK, tid);
            stage_async<256, 64, PAD64>(s1 + ST_BH, g_VTH + nc, N_TOK, tid);
            stage_async<256, 64, PAD64>(s1 + ST_BL, g_VTL + nc, N_TOK, tid);
            CP_COMMIT();
            CP_WAIT1();
        } else {
            CP_WAIT0();
        }
        __syncthreads();
        uint32_t s0 = sb + (ch & 1) * ST_SZ;
        gemm_chunk<4, PAD64>(c, s0 + ST_AH, s0 + ST_AL, s0 + ST_BH, s0 + ST_BL, lane, m0, n0);
        __syncthreads();
    }

    // epilogue: KVT[b][v][m] = (D[m][v] + eps*SV[v]) / sqrt(m)
    float* dbuf = (float*)smem;                    // [128][257]
    float* sv   = (float*)(smem + 131584);         // [256]
    frag_to_dbuf(dbuf, c, lane, m0, n0);
    if (tid < 256) {
        const float* P = g_SVp + (size_t)(4 * b) * 256 + tid;
        sv[tid] = ((P[0] + P[256]) + (P[512] + P[768])) * EPS_PHI;
    }
    __syncthreads();
#pragma unroll 4
    for (int i = 0; i < 32; i++) {
        int f = i * 512 + tid, v = f >> 6, mp = (f & 63) * 2;
        float base = sv[v];
        float v0 = (dbuf[mp * 257 + v] + base) * INV_SQRT_M;
        float v1 = (dbuf[(mp + 1) * 257 + v] + base) * INV_SQRT_M;
        uint32_t hw, lw;
        split_pair(v0, v1, hw, lw);
        *(uint32_t*)&g_KVTH[((size_t)b * DV + v) * MF + m0g + mp] = hw;
        *(uint32_t*)&g_KVTL[((size_t)b * DV + v) * MF + m0g + mp] = lw;
    }
}

// ---------------- norm[i] = Qp[i] . Ksum[seg] + eps ----------------
__global__ __launch_bounds__(256)
void norm_kernel()
{
    __shared__ float wt[4];
    const int tid = threadIdx.x, ty = tid >> 5, tx = tid & 31;
    const int row0 = blockIdx.x * 8;
    const int row = row0 + ty;
    const int b = row0 >> 9;
    if (tid < 4) wt[tid] = __expf(g_bmax[(row0 >> 9) * 4 + tid] - o2f(g_segmax[b]));
    __syncthreads();

    const int m8 = tx * 8;
    uint4 hq = *(const uint4*)&g_QpH[(size_t)row * MF + m8];
    uint4 lq = *(const uint4*)&g_QpL[(size_t)row * MF + m8];
    const uint16_t* hp = (const uint16_t*)&hq;
    const uint16_t* lp = (const uint16_t*)&lq;
    float dot = 0.f;
#pragma unroll
    for (int j = 0; j < 8; j++) {
        int m = m8 + j;
        float k = (g_W[(4 * b + 0) * 256 + m] * wt[0] + g_W[(4 * b + 1) * 256 + m] * wt[1]
                 + g_W[(4 * b + 2) * 256 + m] * wt[2] + g_W[(4 * b + 3) * 256 + m] * wt[3]
                 + 512.0f * EPS_PHI) * INV_SQRT_M;
        dot += from2(hp[j], lp[j]) * k;
    }
    dot = warpSum(dot);
    if (tx == 0) g_norm[row] = dot + EPS_NORM;
}

// ---------------- out: D[row=128][v=256] = Qp @ KVT^T, /norm, pipelined ----------------
__global__ __launch_bounds__(512, 1)
void out_kernel(float* __restrict__ Out)
{
    extern __shared__ char smem[];
    const uint32_t sb = smem_u32(smem);
    const int tid = threadIdx.x, wid = tid >> 5, lane = tid & 31;
    const int b = blockIdx.x >> 2, rt = blockIdx.x & 3;
    const int row0 = b * NPER + rt * 128;
    const int m0 = (wid & 3) * 32, n0 = (wid >> 2) * 64;

    float c[2][8][4];
#pragma unroll
    for (int mt = 0; mt < 2; mt++)
#pragma unroll
        for (int nt = 0; nt < 8; nt++)
#pragma unroll
            for (int q = 0; q < 4; q++) c[mt][nt][q] = 0.f;

    {
        uint32_t s0 = sb;
        stage_async<128, 64, PAD64>(s0 + ST_AH, g_QpH + (size_t)row0 * MF, MF, tid);
        stage_async<128, 64, PAD64>(s0 + ST_AL, g_QpL + (size_t)row0 * MF, MF, tid);
        stage_async<256, 64, PAD64>(s0 + ST_BH, g_KVTH + (size_t)b * DV * MF, MF, tid);
        stage_async<256, 64, PAD64>(s0 + ST_BL, g_KVTL + (size_t)b * DV * MF, MF, tid);
        CP_COMMIT();
    }
    for (int ch = 0; ch < 4; ch++) {
        if (ch < 3) {
            uint32_t s1 = sb + ((ch + 1) & 1) * ST_SZ;
            int k0 = (ch + 1) * 64;
            stage_async<128, 64, PAD64>(s1 + ST_AH, g_QpH + (size_t)row0 * MF + k0, MF, tid);
            stage_async<128, 64, PAD64>(s1 + ST_AL, g_QpL + (size_t)row0 * MF + k0, MF, tid);
            stage_async<256, 64, PAD64>(s1 + ST_BH, g_KVTH + (size_t)b * DV * MF + k0, MF, tid);
            stage_async<256, 64, PAD64>(s1 + ST_BL, g_KVTL + (size_t)b * DV * MF + k0, MF, tid);
            CP_COMMIT();
            CP_WAIT1();
        } else {
            CP_WAIT0();
        }
        __syncthreads();
        uint32_t s0 = sb + (ch & 1) * ST_SZ;
        gemm_chunk<4, PAD64>(c, s0 + ST_AH, s0 + ST_AL, s0 + ST_BH, s0 + ST_BL, lane, m0, n0);
        __syncthreads();
    }

    float* dbuf   = (float*)smem;                  // [128][257]
    float* nrm_sm = (float*)(smem + 131584);       // [128]
    frag_to_dbuf(dbuf, c, lane, m0, n0);
    if (tid < 128) nrm_sm[tid] = 1.0f / g_norm[row0 + tid];
    __syncthreads();
#pragma unroll
    for (int i = 0; i < 16; i++) {
        int f = i * 512 + tid, rr = f >> 6, c4 = (f & 63) * 4;
        float inv = nrm_sm[rr];
        float4 o = make_float4(dbuf[rr * 257 + c4] * inv, dbuf[rr * 257 + c4 + 1] * inv,
                               dbuf[rr * 257 + c4 + 2] * inv, dbuf[rr * 257 + c4 + 3] * inv);
        *(float4*)(Out + (size_t)(row0 + rr) * DV + c4) = o;
    }
}

// ---------------- launch ----------------
#define OMT_SMEM  131584
#define VT_SMEM   (128 * 129 * 4 + 512)

extern "C" void kernel_launch(void* const* d_in, const int* in_sizes, int n_in,
                              void* d_out, int out_size)
{
    (void)in_sizes; (void)n_in; (void)out_size;
    const float* Q     = (const float*)d_in[0];
    const float* K     = (const float*)d_in[1];
    const float* V     = (const float*)d_in[2];
    const float* omega = (const float*)d_in[3];
    float* Out = (float*)d_out;

    cudaFuncSetAttribute(omT_kernel,    cudaFuncAttributeMaxDynamicSharedMemorySize, OMT_SMEM);
    cudaFuncSetAttribute(vT_kernel,     cudaFuncAttributeMaxDynamicSharedMemorySize, VT_SMEM);
    cudaFuncSetAttribute(phi_kernel<1>, cudaFuncAttributeMaxDynamicSharedMemorySize, PHI_SMEM);
    cudaFuncSetAttribute(phi_kernel<0>, cudaFuncAttributeMaxDynamicSharedMemorySize, PHI_SMEM);
    cudaFuncSetAttribute(kv_kernel,     cudaFuncAttributeMaxDynamicSharedMemorySize, PIPE_SMEM);
    cudaFuncSetAttribute(out_kernel,    cudaFuncAttributeMaxDynamicSharedMemorySize, PIPE_SMEM);

    init_kernel<<<1, 64>>>();
    omT_kernel<<<1, 256, OMT_SMEM>>>(omega);
    phi_kernel<1><<<256, 512, PHI_SMEM>>>(Q);
    phi_kernel<0><<<256, 512, PHI_SMEM>>>(K);
    vT_kernel<<<dim3(256, 2), 256, VT_SMEM>>>(V);
    kv_kernel<<<128, 512, PIPE_SMEM>>>();
    norm_kernel<<<N_TOK / 8, 256>>>();
    out_kernel<<<256, 512, PIPE_SMEM>>>(Out);
}

// round 7
// speedup vs baseline: 2.0427x; 1.1542x over previous
#include <cuda_runtime.h>
#include <cuda_bf16.h>
#include <cstdint>

#define N_TOK   32768
#define NBATCH  64
#define NPER    512
#define DQK     128
#define MF      256
#define DV      256
#define SP      72    /* bf16 row stride for 64-col smem tiles (144B, conflict-free) */

#define INV_D4      0.29730177875068026f
#define INV_SQRT_M  0.0625f
#define EPS_PHI     1e-4f
#define EPS_NORM    1e-8f

// ---------------- scratch ----------------
__device__ uint16_t g_QpH [(size_t)N_TOK * MF], g_QpL [(size_t)N_TOK * MF];   // [tok][feat]
__device__ uint16_t g_KpTH[(size_t)MF * N_TOK], g_KpTL[(size_t)MF * N_TOK];   // Kp0^T [feat][tok]
__device__ uint16_t g_VTH [(size_t)DV * N_TOK], g_VTL [(size_t)DV * N_TOK];   // (s*V)^T [v][tok]
__device__ uint16_t g_omTH[(size_t)MF * DQK],   g_omTL[(size_t)MF * DQK];
__device__ uint16_t g_KVTH[(size_t)NBATCH * DV * MF], g_KVTL[(size_t)NBATCH * DV * MF];
__device__ float    g_rowmax[N_TOK];
__device__ float    g_bmax[512];                 // per 64-token tile
__device__ unsigned g_segmax[NBATCH];
__device__ float    g_W  [512 * MF];             // weighted Kp0 colsum per 64-tok tile
__device__ float    g_SVp[256 * DV];             // unweighted V colsum per 128-tok tile
__device__ float    g_norm[N_TOK];

// ---------------- helpers ----------------
__device__ __forceinline__ uint32_t smem_u32(const void* p) {
    uint32_t a;
    asm("{ .reg .u64 t; cvta.to.shared.u64 t, %1; cvt.u32.u64 %0, t; }" : "=r"(a) : "l"(p));
    return a;
}
__device__ __forceinline__ void ldsm4(uint32_t* r, uint32_t a) {
    asm volatile("ldmatrix.sync.aligned.m8n8.x4.shared.b16 {%0,%1,%2,%3}, [%4];"
        : "=r"(r[0]), "=r"(r[1]), "=r"(r[2]), "=r"(r[3]) : "r"(a));
}
__device__ __forceinline__ void mma16816(float* c, const uint32_t* a, const uint32_t* b) {
    asm volatile("mma.sync.aligned.m16n8k16.row.col.f32.bf16.bf16.f32 "
        "{%0,%1,%2,%3}, {%4,%5,%6,%7}, {%8,%9}, {%0,%1,%2,%3};"
        : "+f"(c[0]), "+f"(c[1]), "+f"(c[2]), "+f"(c[3])
        : "r"(a[0]), "r"(a[1]), "r"(a[2]), "r"(a[3]), "r"(b[0]), "r"(b[1]));
}
__device__ __forceinline__ void split1(float v, uint16_t& h, uint16_t& l) {
    __nv_bfloat16 hh = __float2bfloat16(v);
    __nv_bfloat16 ll = __float2bfloat16(v - __bfloat162float(hh));
    h = __bfloat16_as_ushort(hh); l = __bfloat16_as_ushort(ll);
}
__device__ __forceinline__ void split_pair(float a, float b, uint32_t& hw, uint32_t& lw) {
    uint16_t h0, l0, h1, l1;
    split1(a, h0, l0); split1(b, h1, l1);
    hw = (uint32_t)h0 | ((uint32_t)h1 << 16);
    lw = (uint32_t)l0 | ((uint32_t)l1 << 16);
}
__device__ __forceinline__ float from2(uint16_t h, uint16_t l) {
    return __bfloat162float(__ushort_as_bfloat16(h)) + __bfloat162float(__ushort_as_bfloat16(l));
}
__device__ __forceinline__ unsigned f2o(float f) {
    unsigned u = __float_as_uint(f);
    return (u & 0x80000000u) ? ~u : (u | 0x80000000u);
}
__device__ __forceinline__ float o2f(unsigned u) {
    return (u & 0x80000000u) ? __uint_as_float(u & 0x7fffffffu) : __uint_as_float(~u);
}
__device__ __forceinline__ float warpSum(float v) {
#pragma unroll
    for (int o = 16; o > 0; o >>= 1) v += __shfl_xor_sync(0xffffffffu, v, o);
    return v;
}
__device__ __forceinline__ float warpMax(float v) {
#pragma unroll
    for (int o = 16; o > 0; o >>= 1) v = fmaxf(v, __shfl_xor_sync(0xffffffffu, v, o));
    return v;
}
#define CP_COMMIT() asm volatile("cp.async.commit_group;" ::: "memory")
#define CP_WAIT0()  asm volatile("cp.async.wait_group 0;" ::: "memory")

// stage ROWS x 64 u16 tile via cp.async, smem row stride SP u16, THREADS threads
template <int ROWS, int THREADS>
__device__ __forceinline__ void stage_async(uint32_t sdst, const uint16_t* __restrict__ g,
                                            size_t stride, int tid)
{
    constexpr int ITER = ROWS * 8 / THREADS;
#pragma unroll
    for (int i = 0; i < ITER; i++) {
        int idx = i * THREADS + tid;
        int r = idx >> 3, ck = idx & 7;
        uint32_t sa = sdst + (uint32_t)(r * SP * 2 + ck * 16);
        const void* ga = (const void*)(g + (size_t)r * stride + ck * 8);
        asm volatile("cp.async.cg.shared.global [%0], [%1], 16;" :: "r"(sa), "l"(ga));
    }
}

// ---------------- warp-tiled bf16x3 GEMM: one 64-wide K chunk ----------------
// Warp tile 32x64. C = Ah*Bh + Al*Bh + Ah*Bl. m0/n0 from caller's warp layout.
__device__ __forceinline__ void gemm_chunk(float c[2][8][4],
    uint32_t Ahi, uint32_t Alo, uint32_t Bhi, uint32_t Blo, int lane, int m0, int n0)
{
    const uint32_t ao0 = (uint32_t)((m0 + (lane & 15)) * SP + (lane >> 4) * 8) * 2u;
    const uint32_t bo0 = (uint32_t)((n0 + ((lane >> 4) << 3) + (lane & 7)) * SP
                                    + ((lane >> 3) & 1) * 8) * 2u;
#pragma unroll
    for (int ks = 0; ks < 4; ks++) {
        uint32_t ah[2][4], al[2][4];
        ldsm4(ah[0], Ahi + ao0 + ks * 32);
        ldsm4(ah[1], Ahi + ao0 + 16 * SP * 2 + ks * 32);
        ldsm4(al[0], Alo + ao0 + ks * 32);
        ldsm4(al[1], Alo + ao0 + 16 * SP * 2 + ks * 32);
#pragma unroll
        for (int n2 = 0; n2 < 4; n2++) {
            uint32_t bh[4], bl[4];
            ldsm4(bh, Bhi + bo0 + n2 * 16 * SP * 2 + ks * 32);
            ldsm4(bl, Blo + bo0 + n2 * 16 * SP * 2 + ks * 32);
#pragma unroll
            for (int mt = 0; mt < 2; mt++) {
                mma16816(c[mt][n2 * 2],     ah[mt], &bh[0]);
                mma16816(c[mt][n2 * 2],     al[mt], &bh[0]);
                mma16816(c[mt][n2 * 2],     ah[mt], &bl[0]);
                mma16816(c[mt][n2 * 2 + 1], ah[mt], &bh[2]);
                mma16816(c[mt][n2 * 2 + 1], al[mt], &bh[2]);
                mma16816(c[mt][n2 * 2 + 1], ah[mt], &bl[2]);
            }
        }
    }
}

// fragments -> f32 smem dbuf, row stride DS
template <int DS>
__device__ __forceinline__ void frag_to_dbuf(float* dbuf, const float c[2][8][4],
                                             int lane, int m0, int n0)
{
    int g = lane >> 2, j = lane & 3;
#pragma unroll
    for (int mt = 0; mt < 2; mt++)
#pragma unroll
        for (int nt = 0; nt < 8; nt++) {
            int r0 = m0 + mt * 16 + g, cc = n0 + nt * 8 + j * 2;
            dbuf[r0 * DS + cc]           = c[mt][nt][0];
            dbuf[r0 * DS + cc + 1]       = c[mt][nt][1];
            dbuf[(r0 + 8) * DS + cc]     = c[mt][nt][2];
            dbuf[(r0 + 8) * DS + cc + 1] = c[mt][nt][3];
        }
}

// ---------------- init ----------------
__global__ void init_kernel() {
    if (threadIdx.x < NBATCH) g_segmax[threadIdx.x] = 0u;
}

// ---------------- omega^T: [128k][256m] f32 -> omT planes [m][k] ----------------
__global__ __launch_bounds__(256)
void omT_kernel(const float* __restrict__ omega) {
    extern __shared__ char smem[];
    float* tile = (float*)smem;                       // [128][257]
    const int tid = threadIdx.x;
    for (int i = 0; i < 128; i++) {
        int f = i * 256 + tid, k = f >> 8, n = f & 255;
        tile[k * 257 + n] = omega[k * MF + n];
    }
    __syncthreads();
    for (int i = 0; i < 64; i++) {
        int f = i * 256 + tid, m = f >> 6, k2 = (f & 63) * 2;
        uint32_t hw, lw;
        split_pair(tile[k2 * 257 + m], tile[(k2 + 1) * 257 + m], hw, lw);
        *(uint32_t*)&g_omTH[m * DQK + k2] = hw;
        *(uint32_t*)&g_omTL[m * DQK + k2] = lw;
    }
}

// ---------------- vT: (s*V)^T planes + unweighted V colsum partials ----------------
__global__ __launch_bounds__(256)
void vT_kernel(const float* __restrict__ V) {
    extern __shared__ char smem[];
    float* tile = (float*)smem;                       // [128][129]
    float* s_sm = (float*)(smem + 128 * 129 * 4);     // [128]
    const int tid = threadIdx.x;
    const int nt = blockIdx.x, n0 = nt * 128, v0 = blockIdx.y * 128;
    if (tid < 128) s_sm[tid] = __expf(g_rowmax[n0 + tid] - o2f(g_segmax[n0 >> 9]));
    for (int i = 0; i < 64; i++) {
        int f = i * 256 + tid, n = f >> 7, v = f & 127;
        tile[n * 129 + v] = V[(size_t)(n0 + n) * DV + v0 + v];
    }
    __syncthreads();
    for (int i = 0; i < 32; i++) {
        int f = i * 256 + tid, v = f >> 6, np = (f & 63) * 2;
        uint32_t hw, lw;
        split_pair(tile[np * 129 + v] * s_sm[np],
                   tile[(np + 1) * 129 + v] * s_sm[np + 1], hw, lw);
        *(uint32_t*)&g_VTH[(size_t)(v0 + v) * N_TOK + n0 + np] = hw;
        *(uint32_t*)&g_VTL[(size_t)(v0 + v) * N_TOK + n0 + np] = lw;
    }
    if (tid < 128) {
        float s = 0.f;
#pragma unroll 4
        for (int n = 0; n < 128; n++) s += tile[n * 129 + tid];
        g_SVp[nt * 256 + v0 + tid] = s;
    }
}

// ---------------- phi (fused Q+K): 64-tok x 256-feat tile, K in 2x64 chunks ----------------
#define PHI_A_HI  2048
#define PHI_A_LO  (PHI_A_HI + 9216)
#define PHI_B_HI  (PHI_A_LO + 9216)
#define PHI_B_LO  (PHI_B_HI + 36864)
#define PHI_SMEM  (PHI_B_LO + 36864)    /* 94208 */

__global__ __launch_bounds__(256, 2)
void phi_kernel(const float* __restrict__ Q, const float* __restrict__ K)
{
    extern __shared__ char smem[];
    const uint32_t sb = smem_u32(smem);
    const int tid = threadIdx.x, wid = tid >> 5, lane = tid & 31;
    const bool isq = blockIdx.x < 512;
    const int tile = blockIdx.x & 511;
    const int row0 = tile * 64;
    const float* X = isq ? Q : K;
    const int m0 = (wid & 1) * 32, n0 = (wid >> 1) * 64, warpN = wid >> 1;

    float* h_sm    = (float*)smem;               // [64]
    float* rmax_sm = (float*)(smem + 256);       // [64]
    float* rmaxp   = (float*)(smem + 512);       // [64][4]
    float* wm_sm   = (float*)(smem + 1536);      // [2]
    float* bmax_s  = (float*)(smem + 1568);      // [1]
    float* w_sm    = (float*)(smem + 1600);      // [64]
    float* dbuf    = (float*)(smem + PHI_A_HI);  // [64][257] (reuses A/B after gemm)

    float c[2][8][4];
#pragma unroll
    for (int mt = 0; mt < 2; mt++)
#pragma unroll
        for (int nt = 0; nt < 8; nt++)
#pragma unroll
            for (int q = 0; q < 4; q++) c[mt][nt][q] = 0.f;

    const int arow = tid >> 2, aq = tid & 3;
#pragma unroll
    for (int ck = 0; ck < 2; ck++) {
        stage_async<256, 256>(sb + PHI_B_HI, g_omTH + ck * 64, DQK, tid);
        stage_async<256, 256>(sb + PHI_B_LO, g_omTL + ck * 64, DQK, tid);
        CP_COMMIT();
        // A: load X chunk, scale, h partial, split hi/lo
        const float4* xr = (const float4*)(X + (size_t)(row0 + arow) * DQK + ck * 64 + aq * 16);
        float hp = 0.f;
#pragma unroll
        for (int j = 0; j < 4; j++) {
            float4 v = xr[j];
            v.x *= INV_D4; v.y *= INV_D4; v.z *= INV_D4; v.w *= INV_D4;
            hp += v.x * v.x + v.y * v.y + v.z * v.z + v.w * v.w;
            uint32_t hwA, lwA, hwB, lwB;
            split_pair(v.x, v.y, hwA, lwA);
            split_pair(v.z, v.w, hwB, lwB);
            uint32_t off = (uint32_t)(arow * SP + aq * 16 + j * 4) * 2u;
            *(uint2*)(smem + PHI_A_HI + off) = make_uint2(hwA, hwB);
            *(uint2*)(smem + PHI_A_LO + off) = make_uint2(lwA, lwB);
        }
        hp += __shfl_xor_sync(0xffffffffu, hp, 1);
        hp += __shfl_xor_sync(0xffffffffu, hp, 2);
        if ((lane & 3) == 0) {
            if (ck == 0) h_sm[arow] = 0.5f * hp;
            else         h_sm[arow] += 0.5f * hp;
        }
        CP_WAIT0();
        __syncthreads();
        gemm_chunk(c, sb + PHI_A_HI, sb + PHI_A_LO, sb + PHI_B_HI, sb + PHI_B_LO,
                   lane, m0, n0);
        __syncthreads();
    }

    // rowmax from fragments
    float rmx[2][2] = {{-3.0e38f, -3.0e38f}, {-3.0e38f, -3.0e38f}};
#pragma unroll
    for (int mt = 0; mt < 2; mt++)
#pragma unroll
        for (int nt = 0; nt < 8; nt++) {
            rmx[mt][0] = fmaxf(rmx[mt][0], fmaxf(c[mt][nt][0], c[mt][nt][1]));
            rmx[mt][1] = fmaxf(rmx[mt][1], fmaxf(c[mt][nt][2], c[mt][nt][3]));
        }
#pragma unroll
    for (int mt = 0; mt < 2; mt++)
#pragma unroll
        for (int hh = 0; hh < 2; hh++) {
            float v = rmx[mt][hh];
            v = fmaxf(v, __shfl_xor_sync(0xffffffffu, v, 1));
            v = fmaxf(v, __shfl_xor_sync(0xffffffffu, v, 2));
            rmx[mt][hh] = v;
        }
    {
        int g = lane >> 2;
        if ((lane & 3) == 0) {
            rmaxp[(m0 + g) * 4 + warpN]      = rmx[0][0];
            rmaxp[(m0 + g + 8) * 4 + warpN]  = rmx[0][1];
            rmaxp[(m0 + 16 + g) * 4 + warpN] = rmx[1][0];
            rmaxp[(m0 + 24 + g) * 4 + warpN] = rmx[1][1];
        }
    }
    __syncthreads();
    if (tid < 64) {
        float rm = fmaxf(fmaxf(rmaxp[tid * 4], rmaxp[tid * 4 + 1]),
                         fmaxf(rmaxp[tid * 4 + 2], rmaxp[tid * 4 + 3]));
        rmax_sm[tid] = rm;
        if (!isq) {
            g_rowmax[row0 + tid] = rm;
            float bm = warpMax(rm);
            if (lane == 0) wm_sm[wid] = bm;
        }
    }
    __syncthreads();
    if (!isq) {
        if (tid == 0) {
            float bm = fmaxf(wm_sm[0], wm_sm[1]);
            bmax_s[0] = bm;
            g_bmax[tile] = bm;
            atomicMax(&g_segmax[tile >> 3], f2o(bm));
        }
        __syncthreads();
        if (tid < 64) w_sm[tid] = __expf(rmax_sm[tid] - bmax_s[0]);
    }

    if (isq) {
        // Qp: exp + eps + scale, direct plane stores
        int g = lane >> 2, j = lane & 3;
#pragma unroll
        for (int mt = 0; mt < 2; mt++) {
            int r0 = m0 + mt * 16 + g, r1 = r0 + 8;
            float hm0 = h_sm[r0] + rmax_sm[r0];
            float hm1 = h_sm[r1] + rmax_sm[r1];
#pragma unroll
            for (int nt = 0; nt < 8; nt++) {
                int col = n0 + nt * 8 + j * 2;
                float v0 = (__expf(c[mt][nt][0] - hm0) + EPS_PHI) * INV_SQRT_M;
                float v1 = (__expf(c[mt][nt][1] - hm0) + EPS_PHI) * INV_SQRT_M;
                float v2 = (__expf(c[mt][nt][2] - hm1) + EPS_PHI) * INV_SQRT_M;
                float v3 = (__expf(c[mt][nt][3] - hm1) + EPS_PHI) * INV_SQRT_M;
                uint32_t hw, lw;
                split_pair(v0, v1, hw, lw);
                *(uint32_t*)&g_QpH[(size_t)(row0 + r0) * MF + col] = hw;
                *(uint32_t*)&g_QpL[(size_t)(row0 + r0) * MF + col] = lw;
                split_pair(v2, v3, hw, lw);
                *(uint32_t*)&g_QpH[(size_t)(row0 + r1) * MF + col] = hw;
                *(uint32_t*)&g_QpL[(size_t)(row0 + r1) * MF + col] = lw;
            }
        }
    } else {
        // Kp0 = exp(U - h - rowmax) -> dbuf, transposed plane stores + W partial
        int g = lane >> 2;
        float e[2][8][4];
#pragma unroll
        for (int mt = 0; mt < 2; mt++) {
            int r0 = m0 + mt * 16 + g, r1 = r0 + 8;
            float hm0 = h_sm[r0] + rmax_sm[r0];
            float hm1 = h_sm[r1] + rmax_sm[r1];
#pragma unroll
            for (int nt = 0; nt < 8; nt++) {
                e[mt][nt][0] = __expf(c[mt][nt][0] - hm0);
                e[mt][nt][1] = __expf(c[mt][nt][1] - hm0);
                e[mt][nt][2] = __expf(c[mt][nt][2] - hm1);
                e[mt][nt][3] = __expf(c[mt][nt][3] - hm1);
            }
        }
        __syncthreads();
        frag_to_dbuf<257>(dbuf, e, lane, m0, n0);
        __syncthreads();
        // KpT planes: [feat][tok], 64 tokens per tile
#pragma unroll 4
        for (int i = 0; i < 32; i++) {
            int f = i * 256 + tid, feat = f >> 5, tp = (f & 31) * 2;
            uint32_t hw, lw;
            split_pair(dbuf[tp * 257 + feat], dbuf[(tp + 1) * 257 + feat], hw, lw);
            *(uint32_t*)&g_KpTH[(size_t)feat * N_TOK + row0 + tp] = hw;
            *(uint32_t*)&g_KpTL[(size_t)feat * N_TOK + row0 + tp] = lw;
        }
        // W[feat] = sum_tok Kp0[tok][feat] * w[tok]
        float s = 0.f;
#pragma unroll 4
        for (int t = 0; t < 64; t++) s += dbuf[t * 257 + tid] * w_sm[t];
        g_W[tile * 256 + tid] = s;
    }
}

// ---------------- kv: D[m=128][v=128] = sum_n KpT[m][n]*(sV)T[v][n] ----------------
#define G_A_HI  0
#define G_A_LO  18432
#define G_B_HI  36864
#define G_B_LO  55296
#define G_SMEM  73728

__global__ __launch_bounds__(256, 2)
void kv_kernel()
{
    extern __shared__ char smem[];
    const uint32_t sb = smem_u32(smem);
    const int tid = threadIdx.x, wid = tid >> 5, lane = tid & 31;
    const int b = blockIdx.x >> 2, mt_ = (blockIdx.x >> 1) & 1, vt = blockIdx.x & 1;
    const int m0g = mt_ * 128, v0 = vt * 128;
    const int m0 = (wid & 3) * 32, n0 = (wid >> 2) * 64;
    const size_t nb = (size_t)b * NPER;

    float c[2][8][4];
#pragma unroll
    for (int mt = 0; mt < 2; mt++)
#pragma unroll
        for (int nt = 0; nt < 8; nt++)
#pragma unroll
            for (int q = 0; q < 4; q++) c[mt][nt][q] = 0.f;

    for (int ch = 0; ch < 8; ch++) {
        size_t nc = nb + ch * 64;
        stage_async<128, 256>(sb + G_A_HI, g_KpTH + (size_t)m0g * N_TOK + nc, N_TOK, tid);
        stage_async<128, 256>(sb + G_A_LO, g_KpTL + (size_t)m0g * N_TOK + nc, N_TOK, tid);
        stage_async<128, 256>(sb + G_B_HI, g_VTH + (size_t)v0 * N_TOK + nc, N_TOK, tid);
        stage_async<128, 256>(sb + G_B_LO, g_VTL + (size_t)v0 * N_TOK + nc, N_TOK, tid);
        CP_COMMIT();
        CP_WAIT0();
        __syncthreads();
        gemm_chunk(c, sb + G_A_HI, sb + G_A_LO, sb + G_B_HI, sb + G_B_LO, lane, m0, n0);
        __syncthreads();
    }

    // epilogue: KVT[b][v][m] = (D[m][v] + eps*SV[v]) / sqrt(m)
    float* dbuf = (float*)smem;                    // [128][129]
    float* sv   = (float*)(smem + 66048);          // [128]
    frag_to_dbuf<129>(dbuf, c, lane, m0, n0);
    if (tid < 128) {
        const float* P = g_SVp + (size_t)(4 * b) * 256 + v0 + tid;
        sv[tid] = ((P[0] + P[256]) + (P[512] + P[768])) * EPS_PHI;
    }
    __syncthreads();
#pragma unroll 4
    for (int i = 0; i < 32; i++) {
        int f = i * 256 + tid, v = f >> 6, mp = (f & 63) * 2;
        float base = sv[v];
        float v0f = (dbuf[mp * 129 + v] + base) * INV_SQRT_M;
        float v1f = (dbuf[(mp + 1) * 129 + v] + base) * INV_SQRT_M;
        uint32_t hw, lw;
        split_pair(v0f, v1f, hw, lw);
        *(uint32_t*)&g_KVTH[((size_t)b * DV + v0 + v) * MF + m0g + mp] = hw;
        *(uint32_t*)&g_KVTL[((size_t)b * DV + v0 + v) * MF + m0g + mp] = lw;
    }
}

// ---------------- norm[i] = Qp[i] . Ksum[seg] + eps ----------------
__global__ __launch_bounds__(256)
void norm_kernel()
{
    __shared__ float wt[8];
    __shared__ float ksum[256];
    const int tid = threadIdx.x, ty = tid >> 5, tx = tid & 31;
    const int row0 = blockIdx.x * 8;
    const int row = row0 + ty;
    const int b = row0 >> 9;
    if (tid < 8) wt[tid] = __expf(g_bmax[b * 8 + tid] - o2f(g_segmax[b]));
    __syncthreads();
    {
        float s = 0.f;
#pragma unroll
        for (int t = 0; t < 8; t++) s += g_W[(size_t)(8 * b + t) * 256 + tid] * wt[t];
        ksum[tid] = (s + 512.0f * EPS_PHI) * INV_SQRT_M;
    }
    __syncthreads();

    const int m8 = tx * 8;
    uint4 hq = *(const uint4*)&g_QpH[(size_t)row * MF + m8];
    uint4 lq = *(const uint4*)&g_QpL[(size_t)row * MF + m8];
    const uint16_t* hp = (const uint16_t*)&hq;
    const uint16_t* lp = (const uint16_t*)&lq;
    float dot = 0.f;
#pragma unroll
    for (int j = 0; j < 8; j++) dot += from2(hp[j], lp[j]) * ksum[m8 + j];
    dot = warpSum(dot);
    if (tx == 0) g_norm[row] = dot + EPS_NORM;
}

// ---------------- out: D[row=128][v=128] = Qp @ KVT^T, /norm ----------------
__global__ __launch_bounds__(256, 2)
void out_kernel(float* __restrict__ Out)
{
    extern __shared__ char smem[];
    const uint32_t sb = smem_u32(smem);
    const int tid = threadIdx.x, wid = tid >> 5, lane = tid & 31;
    const int b = blockIdx.x >> 3, rt = (blockIdx.x >> 1) & 3, vt = blockIdx.x & 1;
    const int row0 = b * NPER + rt * 128, v0 = vt * 128;
    const int m0 = (wid & 3) * 32, n0 = (wid >> 2) * 64;

    float c[2][8][4];
#pragma unroll
    for (int mt = 0; mt < 2; mt++)
#pragma unroll
        for (int nt = 0; nt < 8; nt++)
#pragma unroll
            for (int q = 0; q < 4; q++) c[mt][nt][q] = 0.f;

    for (int ch = 0; ch < 4; ch++) {
        int k0 = ch * 64;
        stage_async<128, 256>(sb + G_A_HI, g_QpH + (size_t)row0 * MF + k0, MF, tid);
        stage_async<128, 256>(sb + G_A_LO, g_QpL + (size_t)row0 * MF + k0, MF, tid);
        stage_async<128, 256>(sb + G_B_HI, g_KVTH + ((size_t)b * DV + v0) * MF + k0, MF, tid);
        stage_async<128, 256>(sb + G_B_LO, g_KVTL + ((size_t)b * DV + v0) * MF + k0, MF, tid);
        CP_COMMIT();
        CP_WAIT0();
        __syncthreads();
        gemm_chunk(c, sb + G_A_HI, sb + G_A_LO, sb + G_B_HI, sb + G_B_LO, lane, m0, n0);
        __syncthreads();
    }

    float* dbuf   = (float*)smem;                  // [128][129]
    float* nrm_sm = (float*)(smem + 66048);        // [128]
    frag_to_dbuf<129>(dbuf, c, lane, m0, n0);
    if (tid < 128) nrm_sm[tid] = 1.0f / g_norm[row0 + tid];
    __syncthreads();
#pragma unroll
    for (int i = 0; i < 16; i++) {
        int f = i * 256 + tid, rr = f >> 5, c4 = (f & 31) * 4;
        float inv = nrm_sm[rr];
        float4 o = make_float4(dbuf[rr * 129 + c4] * inv, dbuf[rr * 129 + c4 + 1] * inv,
                               dbuf[rr * 129 + c4 + 2] * inv, dbuf[rr * 129 + c4 + 3] * inv);
        *(float4*)(Out + (size_t)(row0 + rr) * DV + v0 + c4) = o;
    }
}

// ---------------- launch ----------------
#define OMT_SMEM  131584
#define VT_SMEM   (128 * 129 * 4 + 512)

extern "C" void kernel_launch(void* const* d_in, const int* in_sizes, int n_in,
                              void* d_out, int out_size)
{
    (void)in_sizes; (void)n_in; (void)out_size;
    const float* Q     = (const float*)d_in[0];
    const float* K     = (const float*)d_in[1];
    const float* V     = (const float*)d_in[2];
    const float* omega = (const float*)d_in[3];
    float* Out = (float*)d_out;

    cudaFuncSetAttribute(omT_kernel,  cudaFuncAttributeMaxDynamicSharedMemorySize, OMT_SMEM);
    cudaFuncSetAttribute(vT_kernel,   cudaFuncAttributeMaxDynamicSharedMemorySize, VT_SMEM);
    cudaFuncSetAttribute(phi_kernel,  cudaFuncAttributeMaxDynamicSharedMemorySize, PHI_SMEM);
    cudaFuncSetAttribute(kv_kernel,   cudaFuncAttributeMaxDynamicSharedMemorySize, G_SMEM);
    cudaFuncSetAttribute(out_kernel,  cudaFuncAttributeMaxDynamicSharedMemorySize, G_SMEM);

    init_kernel<<<1, 64>>>();
    omT_kernel<<<1, 256, OMT_SMEM>>>(omega);
    phi_kernel<<<1024, 256, PHI_SMEM>>>(Q, K);
    vT_kernel<<<dim3(256, 2), 256, VT_SMEM>>>(V);
    kv_kernel<<<256, 256, G_SMEM>>>();
    norm_kernel<<<N_TOK / 8, 256>>>();
    out_kernel<<<512, 256, G_SMEM>>>(Out);
}

// round 8
// speedup vs baseline: 2.1891x; 1.0717x over previous
#include <cuda_runtime.h>
#include <cuda_bf16.h>
#include <cstdint>

#define N_TOK   32768
#define NBATCH  64
#define NPER    512
#define DQK     128
#define MF      256
#define DV      256
#define SP      72    /* bf16 row stride for 64-col smem tiles (144B, conflict-free) */

#define INV_D4      0.29730177875068026f
#define INV_SQRT_M  0.0625f
#define EPS_PHI     1e-4f
#define EPS_NORM    1e-8f

// ---------------- scratch ----------------
__device__ uint16_t g_QpH [(size_t)N_TOK * MF], g_QpL [(size_t)N_TOK * MF];   // [tok][feat]
__device__ uint16_t g_KpTH[(size_t)MF * N_TOK], g_KpTL[(size_t)MF * N_TOK];   // Kp0^T [feat][tok]
__device__ uint16_t g_VTH [(size_t)DV * N_TOK], g_VTL [(size_t)DV * N_TOK];   // (s*V)^T [v][tok]
__device__ uint16_t g_omTH[(size_t)MF * DQK],   g_omTL[(size_t)MF * DQK];
__device__ uint16_t g_KVTH[(size_t)NBATCH * DV * MF], g_KVTL[(size_t)NBATCH * DV * MF];
__device__ float    g_rowmax[N_TOK];
__device__ float    g_bmax[512];                 // per 64-token tile
__device__ unsigned g_segmax[NBATCH];
__device__ float    g_W  [512 * MF];             // weighted Kp0 colsum per 64-tok tile
__device__ float    g_SVp[(size_t)512 * DV];     // unweighted V colsum per 64-tok tile

// ---------------- helpers ----------------
__device__ __forceinline__ uint32_t smem_u32(const void* p) {
    uint32_t a;
    asm("{ .reg .u64 t; cvta.to.shared.u64 t, %1; cvt.u32.u64 %0, t; }" : "=r"(a) : "l"(p));
    return a;
}
__device__ __forceinline__ void ldsm4(uint32_t* r, uint32_t a) {
    asm volatile("ldmatrix.sync.aligned.m8n8.x4.shared.b16 {%0,%1,%2,%3}, [%4];"
        : "=r"(r[0]), "=r"(r[1]), "=r"(r[2]), "=r"(r[3]) : "r"(a));
}
__device__ __forceinline__ void mma16816(float* c, const uint32_t* a, const uint32_t* b) {
    asm volatile("mma.sync.aligned.m16n8k16.row.col.f32.bf16.bf16.f32 "
        "{%0,%1,%2,%3}, {%4,%5,%6,%7}, {%8,%9}, {%0,%1,%2,%3};"
        : "+f"(c[0]), "+f"(c[1]), "+f"(c[2]), "+f"(c[3])
        : "r"(a[0]), "r"(a[1]), "r"(a[2]), "r"(a[3]), "r"(b[0]), "r"(b[1]));
}
__device__ __forceinline__ void split1(float v, uint16_t& h, uint16_t& l) {
    __nv_bfloat16 hh = __float2bfloat16(v);
    __nv_bfloat16 ll = __float2bfloat16(v - __bfloat162float(hh));
    h = __bfloat16_as_ushort(hh); l = __bfloat16_as_ushort(ll);
}
__device__ __forceinline__ void split_pair(float a, float b, uint32_t& hw, uint32_t& lw) {
    uint16_t h0, l0, h1, l1;
    split1(a, h0, l0); split1(b, h1, l1);
    hw = (uint32_t)h0 | ((uint32_t)h1 << 16);
    lw = (uint32_t)l0 | ((uint32_t)l1 << 16);
}
__device__ __forceinline__ float from2(uint16_t h, uint16_t l) {
    return __bfloat162float(__ushort_as_bfloat16(h)) + __bfloat162float(__ushort_as_bfloat16(l));
}
__device__ __forceinline__ unsigned f2o(float f) {
    unsigned u = __float_as_uint(f);
    return (u & 0x80000000u) ? ~u : (u | 0x80000000u);
}
__device__ __forceinline__ float o2f(unsigned u) {
    return (u & 0x80000000u) ? __uint_as_float(u & 0x7fffffffu) : __uint_as_float(~u);
}
__device__ __forceinline__ float warpMax(float v) {
#pragma unroll
    for (int o = 16; o > 0; o >>= 1) v = fmaxf(v, __shfl_xor_sync(0xffffffffu, v, o));
    return v;
}
#define CP_COMMIT() asm volatile("cp.async.commit_group;" ::: "memory")
#define CP_WAIT0()  asm volatile("cp.async.wait_group 0;" ::: "memory")

// stage ROWS x 64 u16 tile via cp.async, smem row stride SP u16 (256 threads)
template <int ROWS>
__device__ __forceinline__ void stage_async(uint32_t sdst, const uint16_t* __restrict__ g,
                                            size_t stride, int tid)
{
    constexpr int ITER = ROWS * 8 / 256;
#pragma unroll
    for (int i = 0; i < ITER; i++) {
        int idx = i * 256 + tid;
        int r = idx >> 3, ck = idx & 7;
        uint32_t sa = sdst + (uint32_t)(r * SP * 2 + ck * 16);
        const void* ga = (const void*)(g + (size_t)r * stride + ck * 8);
        asm volatile("cp.async.cg.shared.global [%0], [%1], 16;" :: "r"(sa), "l"(ga));
    }
}

// ---------------- warp-tiled bf16x3 GEMM: one 64-wide K chunk ----------------
__device__ __forceinline__ void gemm_chunk(float c[2][8][4],
    uint32_t Ahi, uint32_t Alo, uint32_t Bhi, uint32_t Blo, int lane, int m0, int n0)
{
    const uint32_t ao0 = (uint32_t)((m0 + (lane & 15)) * SP + (lane >> 4) * 8) * 2u;
    const uint32_t bo0 = (uint32_t)((n0 + ((lane >> 4) << 3) + (lane & 7)) * SP
                                    + ((lane >> 3) & 1) * 8) * 2u;
#pragma unroll
    for (int ks = 0; ks < 4; ks++) {
        uint32_t ah[2][4], al[2][4];
        ldsm4(ah[0], Ahi + ao0 + ks * 32);
        ldsm4(ah[1], Ahi + ao0 + 16 * SP * 2 + ks * 32);
        ldsm4(al[0], Alo + ao0 + ks * 32);
        ldsm4(al[1], Alo + ao0 + 16 * SP * 2 + ks * 32);
#pragma unroll
        for (int n2 = 0; n2 < 4; n2++) {
            uint32_t bh[4], bl[4];
            ldsm4(bh, Bhi + bo0 + n2 * 16 * SP * 2 + ks * 32);
            ldsm4(bl, Blo + bo0 + n2 * 16 * SP * 2 + ks * 32);
#pragma unroll
            for (int mt = 0; mt < 2; mt++) {
                mma16816(c[mt][n2 * 2],     ah[mt], &bh[0]);
                mma16816(c[mt][n2 * 2],     al[mt], &bh[0]);
                mma16816(c[mt][n2 * 2],     ah[mt], &bl[0]);
                mma16816(c[mt][n2 * 2 + 1], ah[mt], &bh[2]);
                mma16816(c[mt][n2 * 2 + 1], al[mt], &bh[2]);
                mma16816(c[mt][n2 * 2 + 1], ah[mt], &bl[2]);
            }
        }
    }
}

// fragments -> f32 smem dbuf, row stride DS
template <int DS>
__device__ __forceinline__ void frag_to_dbuf(float* dbuf, const float c[2][8][4],
                                             int lane, int m0, int n0)
{
    int g = lane >> 2, j = lane & 3;
#pragma unroll
    for (int mt = 0; mt < 2; mt++)
#pragma unroll
        for (int nt = 0; nt < 8; nt++) {
            int r0 = m0 + mt * 16 + g, cc = n0 + nt * 8 + j * 2;
            dbuf[r0 * DS + cc]           = c[mt][nt][0];
            dbuf[r0 * DS + cc + 1]       = c[mt][nt][1];
            dbuf[(r0 + 8) * DS + cc]     = c[mt][nt][2];
            dbuf[(r0 + 8) * DS + cc + 1] = c[mt][nt][3];
        }
}

// ---------------- omega^T (4 CTAs) + segmax init ----------------
#define OMT_SMEM (128 * 65 * 4)
__global__ __launch_bounds__(256)
void omT_kernel(const float* __restrict__ omega) {
    extern __shared__ char smem[];
    float* tile = (float*)smem;                       // [128][65]
    const int tid = threadIdx.x;
    if (blockIdx.x == 0 && tid < NBATCH) g_segmax[tid] = 0u;
    const int m0 = blockIdx.x * 64;
#pragma unroll
    for (int i = 0; i < 32; i++) {
        int f = i * 256 + tid, k = f >> 6, mm = f & 63;
        tile[k * 65 + mm] = omega[k * MF + m0 + mm];
    }
    __syncthreads();
#pragma unroll
    for (int i = 0; i < 8; i++) {
        int f = i * 256 + tid, mm = f >> 5, kq = (f & 31) * 4;
        uint32_t h0, l0, h1, l1;
        split_pair(tile[kq * 65 + mm],       tile[(kq + 1) * 65 + mm], h0, l0);
        split_pair(tile[(kq + 2) * 65 + mm], tile[(kq + 3) * 65 + mm], h1, l1);
        *(uint2*)&g_omTH[(size_t)(m0 + mm) * DQK + kq] = make_uint2(h0, h1);
        *(uint2*)&g_omTL[(size_t)(m0 + mm) * DQK + kq] = make_uint2(l0, l1);
    }
}

// ---------------- vT: (s*V)^T planes + V colsum partials (64n x 128v tiles) ----------------
#define VT_SMEM (64 * 129 * 4 + 256)
__global__ __launch_bounds__(256)
void vT_kernel(const float* __restrict__ V) {
    extern __shared__ char smem[];
    float* tile = (float*)smem;                       // [64][129]
    float* s_sm = (float*)(smem + 64 * 129 * 4);      // [64]
    const int tid = threadIdx.x;
    const int nt = blockIdx.x, n0 = nt * 64, v0 = blockIdx.y * 128;
    if (tid < 64) s_sm[tid] = __expf(g_rowmax[n0 + tid] - o2f(g_segmax[n0 >> 9]));
#pragma unroll
    for (int i = 0; i < 32; i++) {
        int f = i * 256 + tid, n = f >> 7, v = f & 127;
        tile[n * 129 + v] = V[(size_t)(n0 + n) * DV + v0 + v];
    }
    __syncthreads();
#pragma unroll
    for (int i = 0; i < 8; i++) {
        int f = i * 256 + tid, v = f >> 4, nq = (f & 15) * 4;
        uint32_t h0, l0, h1, l1;
        split_pair(tile[nq * 129 + v] * s_sm[nq],
                   tile[(nq + 1) * 129 + v] * s_sm[nq + 1], h0, l0);
        split_pair(tile[(nq + 2) * 129 + v] * s_sm[nq + 2],
                   tile[(nq + 3) * 129 + v] * s_sm[nq + 3], h1, l1);
        *(uint2*)&g_VTH[(size_t)(v0 + v) * N_TOK + n0 + nq] = make_uint2(h0, h1);
        *(uint2*)&g_VTL[(size_t)(v0 + v) * N_TOK + n0 + nq] = make_uint2(l0, l1);
    }
    if (tid < 128) {
        float s = 0.f;
#pragma unroll 4
        for (int n = 0; n < 64; n++) s += tile[n * 129 + tid];
        g_SVp[(size_t)nt * 256 + v0 + tid] = s;
    }
}

// ---------------- phi (fused Q+K): 64-tok x 256-feat tile, K in 2x64 chunks ----------------
#define PHI_A_HI  2048
#define PHI_A_LO  (PHI_A_HI + 9216)
#define PHI_B_HI  (PHI_A_LO + 9216)
#define PHI_B_LO  (PHI_B_HI + 36864)
#define PHI_SMEM  (PHI_B_LO + 36864)    /* 94208 */

__global__ __launch_bounds__(256, 2)
void phi_kernel(const float* __restrict__ Q, const float* __restrict__ K)
{
    extern __shared__ char smem[];
    const uint32_t sb = smem_u32(smem);
    const int tid = threadIdx.x, wid = tid >> 5, lane = tid & 31;
    const bool isq = blockIdx.x < 512;
    const int tile = blockIdx.x & 511;
    const int row0 = tile * 64;
    const float* X = isq ? Q : K;
    const int m0 = (wid & 1) * 32, n0 = (wid >> 1) * 64, warpN = wid >> 1;

    float* h_sm    = (float*)smem;               // [64]
    float* rmax_sm = (float*)(smem + 256);       // [64]
    float* rmaxp   = (float*)(smem + 512);       // [64][4]
    float* wm_sm   = (float*)(smem + 1536);      // [2]
    float* bmax_s  = (float*)(smem + 1568);      // [1]
    float* w_sm    = (float*)(smem + 1600);      // [64]
    float* dbuf    = (float*)(smem + PHI_A_HI);  // [64][257]

    float c[2][8][4];
#pragma unroll
    for (int mt = 0; mt < 2; mt++)
#pragma unroll
        for (int nt = 0; nt < 8; nt++)
#pragma unroll
            for (int q = 0; q < 4; q++) c[mt][nt][q] = 0.f;

    const int arow = tid >> 2, aq = tid & 3;
#pragma unroll
    for (int ck = 0; ck < 2; ck++) {
        stage_async<256>(sb + PHI_B_HI, g_omTH + ck * 64, DQK, tid);
        stage_async<256>(sb + PHI_B_LO, g_omTL + ck * 64, DQK, tid);
        CP_COMMIT();
        const float4* xr = (const float4*)(X + (size_t)(row0 + arow) * DQK + ck * 64 + aq * 16);
        float hp = 0.f;
#pragma unroll
        for (int j = 0; j < 4; j++) {
            float4 v = xr[j];
            v.x *= INV_D4; v.y *= INV_D4; v.z *= INV_D4; v.w *= INV_D4;
            hp += v.x * v.x + v.y * v.y + v.z * v.z + v.w * v.w;
            uint32_t hwA, lwA, hwB, lwB;
            split_pair(v.x, v.y, hwA, lwA);
            split_pair(v.z, v.w, hwB, lwB);
            uint32_t off = (uint32_t)(arow * SP + aq * 16 + j * 4) * 2u;
            *(uint2*)(smem + PHI_A_HI + off) = make_uint2(hwA, hwB);
            *(uint2*)(smem + PHI_A_LO + off) = make_uint2(lwA, lwB);
        }
        hp += __shfl_xor_sync(0xffffffffu, hp, 1);
        hp += __shfl_xor_sync(0xffffffffu, hp, 2);
        if ((lane & 3) == 0) {
            if (ck == 0) h_sm[arow] = 0.5f * hp;
            else         h_sm[arow] += 0.5f * hp;
        }
        CP_WAIT0();
        __syncthreads();
        gemm_chunk(c, sb + PHI_A_HI, sb + PHI_A_LO, sb + PHI_B_HI, sb + PHI_B_LO,
                   lane, m0, n0);
        __syncthreads();
    }

    float rmx[2][2] = {{-3.0e38f, -3.0e38f}, {-3.0e38f, -3.0e38f}};
#pragma unroll
    for (int mt = 0; mt < 2; mt++)
#pragma unroll
        for (int nt = 0; nt < 8; nt++) {
            rmx[mt][0] = fmaxf(rmx[mt][0], fmaxf(c[mt][nt][0], c[mt][nt][1]));
            rmx[mt][1] = fmaxf(rmx[mt][1], fmaxf(c[mt][nt][2], c[mt][nt][3]));
        }
#pragma unroll
    for (int mt = 0; mt < 2; mt++)
#pragma unroll
        for (int hh = 0; hh < 2; hh++) {
            float v = rmx[mt][hh];
            v = fmaxf(v, __shfl_xor_sync(0xffffffffu, v, 1));
            v = fmaxf(v, __shfl_xor_sync(0xffffffffu, v, 2));
            rmx[mt][hh] = v;
        }
    {
        int g = lane >> 2;
        if ((lane & 3) == 0) {
            rmaxp[(m0 + g) * 4 + warpN]      = rmx[0][0];
            rmaxp[(m0 + g + 8) * 4 + warpN]  = rmx[0][1];
            rmaxp[(m0 + 16 + g) * 4 + warpN] = rmx[1][0];
            rmaxp[(m0 + 24 + g) * 4 + warpN] = rmx[1][1];
        }
    }
    __syncthreads();
    if (tid < 64) {
        float rm = fmaxf(fmaxf(rmaxp[tid * 4], rmaxp[tid * 4 + 1]),
                         fmaxf(rmaxp[tid * 4 + 2], rmaxp[tid * 4 + 3]));
        rmax_sm[tid] = rm;
        if (!isq) {
            g_rowmax[row0 + tid] = rm;
            float bm = warpMax(rm);
            if (lane == 0) wm_sm[wid] = bm;
        }
    }
    __syncthreads();
    if (!isq) {
        if (tid == 0) {
            float bm = fmaxf(wm_sm[0], wm_sm[1]);
            bmax_s[0] = bm;
            g_bmax[tile] = bm;
            atomicMax(&g_segmax[tile >> 3], f2o(bm));
        }
        __syncthreads();
        if (tid < 64) w_sm[tid] = __expf(rmax_sm[tid] - bmax_s[0]);
    }

    if (isq) {
        int g = lane >> 2, j = lane & 3;
#pragma unroll
        for (int mt = 0; mt < 2; mt++) {
            int r0 = m0 + mt * 16 + g, r1 = r0 + 8;
            float hm0 = h_sm[r0] + rmax_sm[r0];
            float hm1 = h_sm[r1] + rmax_sm[r1];
#pragma unroll
            for (int nt = 0; nt < 8; nt++) {
                int col = n0 + nt * 8 + j * 2;
                float v0 = (__expf(c[mt][nt][0] - hm0) + EPS_PHI) * INV_SQRT_M;
                float v1 = (__expf(c[mt][nt][1] - hm0) + EPS_PHI) * INV_SQRT_M;
                float v2 = (__expf(c[mt][nt][2] - hm1) + EPS_PHI) * INV_SQRT_M;
                float v3 = (__expf(c[mt][nt][3] - hm1) + EPS_PHI) * INV_SQRT_M;
                uint32_t hw, lw;
                split_pair(v0, v1, hw, lw);
                *(uint32_t*)&g_QpH[(size_t)(row0 + r0) * MF + col] = hw;
                *(uint32_t*)&g_QpL[(size_t)(row0 + r0) * MF + col] = lw;
                split_pair(v2, v3, hw, lw);
                *(uint32_t*)&g_QpH[(size_t)(row0 + r1) * MF + col] = hw;
                *(uint32_t*)&g_QpL[(size_t)(row0 + r1) * MF + col] = lw;
            }
        }
    } else {
        int g = lane >> 2;
        float e[2][8][4];
#pragma unroll
        for (int mt = 0; mt < 2; mt++) {
            int r0 = m0 + mt * 16 + g, r1 = r0 + 8;
            float hm0 = h_sm[r0] + rmax_sm[r0];
            float hm1 = h_sm[r1] + rmax_sm[r1];
#pragma unroll
            for (int nt = 0; nt < 8; nt++) {
                e[mt][nt][0] = __expf(c[mt][nt][0] - hm0);
                e[mt][nt][1] = __expf(c[mt][nt][1] - hm0);
                e[mt][nt][2] = __expf(c[mt][nt][2] - hm1);
                e[mt][nt][3] = __expf(c[mt][nt][3] - hm1);
            }
        }
        __syncthreads();
        frag_to_dbuf<257>(dbuf, e, lane, m0, n0);
        __syncthreads();
#pragma unroll 4
        for (int i = 0; i < 32; i++) {
            int f = i * 256 + tid, feat = f >> 5, tp = (f & 31) * 2;
            uint32_t hw, lw;
            split_pair(dbuf[tp * 257 + feat], dbuf[(tp + 1) * 257 + feat], hw, lw);
            *(uint32_t*)&g_KpTH[(size_t)feat * N_TOK + row0 + tp] = hw;
            *(uint32_t*)&g_KpTL[(size_t)feat * N_TOK + row0 + tp] = lw;
        }
        float s = 0.f;
#pragma unroll 4
        for (int t = 0; t < 64; t++) s += dbuf[t * 257 + tid] * w_sm[t];
        g_W[tile * 256 + tid] = s;
    }
}

// ---------------- kv: D[m=128][v=128] = sum_n KpT[m][n]*(sV)T[v][n] ----------------
#define G_A_HI  0
#define G_A_LO  18432
#define G_B_HI  36864
#define G_B_LO  55296
#define G_SMEM  73728

__global__ __launch_bounds__(256, 2)
void kv_kernel()
{
    extern __shared__ char smem[];
    const uint32_t sb = smem_u32(smem);
    const int tid = threadIdx.x, wid = tid >> 5, lane = tid & 31;
    const int b = blockIdx.x >> 2, mt_ = (blockIdx.x >> 1) & 1, vt = blockIdx.x & 1;
    const int m0g = mt_ * 128, v0 = vt * 128;
    const int m0 = (wid & 3) * 32, n0 = (wid >> 2) * 64;
    const size_t nb = (size_t)b * NPER;

    float c[2][8][4];
#pragma unroll
    for (int mt = 0; mt < 2; mt++)
#pragma unroll
        for (int nt = 0; nt < 8; nt++)
#pragma unroll
            for (int q = 0; q < 4; q++) c[mt][nt][q] = 0.f;

    for (int ch = 0; ch < 8; ch++) {
        size_t nc = nb + ch * 64;
        stage_async<128>(sb + G_A_HI, g_KpTH + (size_t)m0g * N_TOK + nc, N_TOK, tid);
        stage_async<128>(sb + G_A_LO, g_KpTL + (size_t)m0g * N_TOK + nc, N_TOK, tid);
        stage_async<128>(sb + G_B_HI, g_VTH + (size_t)v0 * N_TOK + nc, N_TOK, tid);
        stage_async<128>(sb + G_B_LO, g_VTL + (size_t)v0 * N_TOK + nc, N_TOK, tid);
        CP_COMMIT();
        CP_WAIT0();
        __syncthreads();
        gemm_chunk(c, sb + G_A_HI, sb + G_A_LO, sb + G_B_HI, sb + G_B_LO, lane, m0, n0);
        __syncthreads();
    }

    float* dbuf = (float*)smem;                    // [128][129]
    float* sv   = (float*)(smem + 66048);          // [128]
    frag_to_dbuf<129>(dbuf, c, lane, m0, n0);
    if (tid < 128) {
        const float* P = g_SVp + (size_t)(8 * b) * 256 + v0 + tid;
        float s = 0.f;
#pragma unroll
        for (int t = 0; t < 8; t++) s += P[t * 256];
        sv[tid] = s * EPS_PHI;
    }
    __syncthreads();
#pragma unroll 4
    for (int i = 0; i < 32; i++) {
        int f = i * 256 + tid, v = f >> 6, mp = (f & 63) * 2;
        float base = sv[v];
        float v0f = (dbuf[mp * 129 + v] + base) * INV_SQRT_M;
        float v1f = (dbuf[(mp + 1) * 129 + v] + base) * INV_SQRT_M;
        uint32_t hw, lw;
        split_pair(v0f, v1f, hw, lw);
        *(uint32_t*)&g_KVTH[((size_t)b * DV + v0 + v) * MF + m0g + mp] = hw;
        *(uint32_t*)&g_KVTL[((size_t)b * DV + v0 + v) * MF + m0g + mp] = lw;
    }
}

// ---------------- out: D = Qp @ KVT^T, norm fused (ksum from g_W) ----------------
#define OUT_KSUM  73728
#define OUT_WT    (OUT_KSUM + 1024)
#define OUT_SMEM  (OUT_WT + 64)

__global__ __launch_bounds__(256, 2)
void out_kernel(float* __restrict__ Out)
{
    extern __shared__ char smem[];
    const uint32_t sb = smem_u32(smem);
    const int tid = threadIdx.x, wid = tid >> 5, lane = tid & 31;
    const int b = blockIdx.x >> 3, rt = (blockIdx.x >> 1) & 3, vt = blockIdx.x & 1;
    const int row0 = b * NPER + rt * 128, v0 = vt * 128;
    const int m0 = (wid & 3) * 32, n0 = (wid >> 2) * 64;
    float* ksum = (float*)(smem + OUT_KSUM);       // [256]
    float* wtp  = (float*)(smem + OUT_WT);         // [8]

    if (tid < 8) wtp[tid] = __expf(g_bmax[b * 8 + tid] - o2f(g_segmax[b]));
    __syncthreads();
    {
        float s = 0.f;
#pragma unroll
        for (int t = 0; t < 8; t++) s += g_W[(size_t)(8 * b + t) * 256 + tid] * wtp[t];
        ksum[tid] = (s + 512.0f * EPS_PHI) * INV_SQRT_M;
    }

    float c[2][8][4];
#pragma unroll
    for (int mt = 0; mt < 2; mt++)
#pragma unroll
        for (int nt = 0; nt < 8; nt++)
#pragma unroll
            for (int q = 0; q < 4; q++) c[mt][nt][q] = 0.f;

    const int qrow = tid >> 1, qoff = (tid & 1) * 32;
    float qd = 0.f;

    for (int ch = 0; ch < 4; ch++) {
        int k0 = ch * 64;
        stage_async<128>(sb + G_A_HI, g_QpH + (size_t)row0 * MF + k0, MF, tid);
        stage_async<128>(sb + G_A_LO, g_QpL + (size_t)row0 * MF + k0, MF, tid);
        stage_async<128>(sb + G_B_HI, g_KVTH + ((size_t)b * DV + v0) * MF + k0, MF, tid);
        stage_async<128>(sb + G_B_LO, g_KVTL + ((size_t)b * DV + v0) * MF + k0, MF, tid);
        CP_COMMIT();
        CP_WAIT0();
        __syncthreads();
        // qdot partial from staged A (Qp hi+lo) against ksum
        {
            const uint16_t* AH = (const uint16_t*)(smem + G_A_HI);
            const uint16_t* AL = (const uint16_t*)(smem + G_A_LO);
            float qp = 0.f;
#pragma unroll
            for (int jq = 0; jq < 8; jq++) {
                uint2 h2 = *(const uint2*)&AH[qrow * SP + qoff + jq * 4];
                uint2 l2 = *(const uint2*)&AL[qrow * SP + qoff + jq * 4];
                const uint16_t* hp = (const uint16_t*)&h2;
                const uint16_t* lp = (const uint16_t*)&l2;
#pragma unroll
                for (int j = 0; j < 4; j++)
                    qp += from2(hp[j], lp[j]) * ksum[k0 + qoff + jq * 4 + j];
            }
            qd += qp;
        }
        gemm_chunk(c, sb + G_A_HI, sb + G_A_LO, sb + G_B_HI, sb + G_B_LO, lane, m0, n0);
        __syncthreads();
    }

    qd += __shfl_xor_sync(0xffffffffu, qd, 1);

    float* dbuf   = (float*)smem;                  // [128][129]
    float* nrm_sm = (float*)(smem + 66048);        // [128]
    frag_to_dbuf<129>(dbuf, c, lane, m0, n0);
    if ((tid & 1) == 0) nrm_sm[qrow] = 1.0f / (qd + EPS_NORM);
    __syncthreads();
#pragma unroll
    for (int i = 0; i < 16; i++) {
        int f = i * 256 + tid, rr = f >> 5, c4 = (f & 31) * 4;
        float inv = nrm_sm[rr];
        float4 o = make_float4(dbuf[rr * 129 + c4] * inv, dbuf[rr * 129 + c4 + 1] * inv,
                               dbuf[rr * 129 + c4 + 2] * inv, dbuf[rr * 129 + c4 + 3] * inv);
        *(float4*)(Out + (size_t)(row0 + rr) * DV + v0 + c4) = o;
    }
}

// ---------------- launch ----------------
extern "C" void kernel_launch(void* const* d_in, const int* in_sizes, int n_in,
                              void* d_out, int out_size)
{
    (void)in_sizes; (void)n_in; (void)out_size;
    const float* Q     = (const float*)d_in[0];
    const float* K     = (const float*)d_in[1];
    const float* V     = (const float*)d_in[2];
    const float* omega = (const float*)d_in[3];
    float* Out = (float*)d_out;

    cudaFuncSetAttribute(omT_kernel,  cudaFuncAttributeMaxDynamicSharedMemorySize, OMT_SMEM);
    cudaFuncSetAttribute(vT_kernel,   cudaFuncAttributeMaxDynamicSharedMemorySize, VT_SMEM);
    cudaFuncSetAttribute(phi_kernel,  cudaFuncAttributeMaxDynamicSharedMemorySize, PHI_SMEM);
    cudaFuncSetAttribute(kv_kernel,   cudaFuncAttributeMaxDynamicSharedMemorySize, G_SMEM);
    cudaFuncSetAttribute(out_kernel,  cudaFuncAttributeMaxDynamicSharedMemorySize, OUT_SMEM);

    omT_kernel<<<4, 256, OMT_SMEM>>>(omega);
    phi_kernel<<<1024, 256, PHI_SMEM>>>(Q, K);
    vT_kernel<<<dim3(512, 2), 256, VT_SMEM>>>(V);
    kv_kernel<<<256, 256, G_SMEM>>>();
    out_kernel<<<512, 256, OUT_SMEM>>>(Out);
}